// round 11
// baseline (speedup 1.0000x reference)
#include <cuda_runtime.h>
#include <cuda_bf16.h>
#include <cuda_fp16.h>
#include <math.h>
#include <stdint.h>

#define BS   128
#define GS   2000
#define E    128
#define KM   4
#define NEGV (-1.0e30f)
#define CLIPV 10.0f

// ---------------- device scratch (static globals; no runtime allocation) ----------------
__device__ unsigned char d_Kc8[(size_t)BS * GS * 512];  // [b][g][K1|K2|K3|K4] e4m3 (131 MB)
__device__ __nv_bfloat16 d_Wb[512 * 128];               // [n=j*128+f][k=e] bf16 (col-major B)
__device__ int   d_vtt[BS * GS];
__device__ float d_q1[BS * E], d_q2[BS * E];
__device__ float d_Qp[BS * 512];                        // [Q1|Q2|Q3|Q4] per b
__device__ float d_hmean[BS * E];
__device__ int   d_ai[BS * 4];
__device__ int   d_kl[BS * 5];
__device__ int   d_kr[BS * 4];
__device__ int   d_nol[BS];
__device__ int   d_stopped[BS];
__device__ float d_ll[BS];
// per-iteration scalar handoff (written by update, read by gru/score of next iter)
__device__ float d_expsum[BS];
__device__ float d_logact[BS];
__device__ int   d_act[BS];        // action_{i-1} (gru gather + mask unset)
__device__ int   d_stopold_g[BS];  // stopped entering iter i-1 (for input_q2 select)
__device__ int   d_nolmod[BS];     // nol_old floored-mod GS
__device__ int   d_va[BS];         // vtt[action_{i-1}]
__device__ int   d_stopnew[BS];
__device__ int   d_allow[BS];
__device__ int   d_ai0g[BS];
__device__ int   d_nextact[BS];    // action for iter i

// ---------------- math helpers ----------------
__device__ __forceinline__ float fast_rcp(float x) {
    float r = __uint_as_float(0x7EF311C3u - __float_as_uint(x));
    r = r * (2.0f - x * r);
    r = r * (2.0f - x * r);
    return r;
}
__device__ __forceinline__ float tanh_fast(float x) {
    // Pade(5,4), clamp 3.6; abs err <= ~1e-3; fma/alu pipes only
    float xc = fminf(fmaxf(x, -3.6f), 3.6f);
    float x2 = xc * xc;
    float num = xc * fmaf(x2, x2 + 105.0f, 945.0f);
    float den = fmaf(x2, fmaf(15.0f, x2, 420.0f), 945.0f);
    return num * fast_rcp(den);
}
__device__ __forceinline__ float sigmoidf_(float x) { return 1.0f / (1.0f + expf(-x)); }

// pack two f32 -> e4m3x2 (byte0 = a, byte1 = b)
__device__ __forceinline__ unsigned short fp8pack(float a, float b) {
    unsigned short p;
    asm("cvt.rn.satfinite.e4m3x2.f32 %0, %1, %2;" : "=h"(p) : "f"(b), "f"(a));
    return p;
}
// 4 e4m3 bytes -> 4 floats (o[0] = byte0 ...)
__device__ __forceinline__ void fp8x4_to_f32(unsigned u, float* o) {
    unsigned h01, h23;
    asm("{\n\t.reg .b16 lo, hi;\n\t"
        "mov.b32 {lo, hi}, %2;\n\t"
        "cvt.rn.f16x2.e4m3x2 %0, lo;\n\t"
        "cvt.rn.f16x2.e4m3x2 %1, hi;\n\t}"
        : "=r"(h01), "=r"(h23) : "r"(u));
    float2 x = __half22float2(*reinterpret_cast<__half2*>(&h01));
    float2 y = __half22float2(*reinterpret_cast<__half2*>(&h23));
    o[0] = x.x; o[1] = x.y; o[2] = y.x; o[3] = y.y;
}

#define LDSM4(r, addr) \
    asm volatile("ldmatrix.sync.aligned.m8n8.x4.shared.b16 {%0,%1,%2,%3}, [%4];" \
                 : "=r"((r)[0]), "=r"((r)[1]), "=r"((r)[2]), "=r"((r)[3]) : "r"(addr))

#define MMA16816(c, a, b0, b1) \
    asm volatile("mma.sync.aligned.m16n8k16.row.col.f32.bf16.bf16.f32 " \
                 "{%0,%1,%2,%3},{%4,%5,%6,%7},{%8,%9},{%0,%1,%2,%3};" \
                 : "+f"((c)[0]), "+f"((c)[1]), "+f"((c)[2]), "+f"((c)[3]) \
                 : "r"((a)[0]), "r"((a)[1]), "r"((a)[2]), "r"((a)[3]), "r"(b0), "r"(b1))

// ---------------- setup kernels ----------------
__global__ void convert_w(const float* __restrict__ W1, const float* __restrict__ W2,
                          const float* __restrict__ W3, const float* __restrict__ W4) {
    int idx = blockIdx.x * blockDim.x + threadIdx.x;    // 65536
    if (idx >= 512 * 128) return;
    int j = idx >> 14, r = idx & 16383;
    const float* W = (j == 0) ? W1 : (j == 1) ? W2 : (j == 2) ? W3 : W4;
    d_Wb[idx] = __float2bfloat16(W[r]);
}

__global__ void hmean_kernel(const float* __restrict__ h) {
    int b = blockIdx.x, t = threadIdx.x;                 // 512 threads
    int e = t & 127, q = t >> 7;
    __shared__ float part[4][128];
    float s = 0.f;
    for (int g = q * 500; g < (q + 1) * 500; g++)
        s += h[((size_t)b * GS + g) * E + e];
    part[q][e] = s;
    __syncthreads();
    if (t < 128)
        d_hmean[b * E + t] = (part[0][t] + part[1][t] + part[2][t] + part[3][t]) * (1.0f / GS);
}

__global__ void vtt_kernel(const int* __restrict__ vt, const int* __restrict__ fixed_action) {
    int b = blockIdx.x, t = threadIdx.x;                 // 256 threads
    int bG = b * GS;
    int vta = vt[bG + fixed_action[b * KM]];             // iter-0 action is fixed
    for (int g = t; g < GS; g += 256) {
        int d = vt[bG + g] - vta;                        // in (-GS, GS)
        d_vtt[bG + g] = (d + GS) % GS;                   // Python floored mod
    }
}

__global__ void init_kernel(const float* __restrict__ W_init, const float* __restrict__ b_init,
                            const float* __restrict__ init_query) {
    int b = blockIdx.x, t = threadIdx.x;                 // 128 threads
    (void)init_query;
    __shared__ __align__(16) float sm[E];
    sm[t] = d_hmean[b * E + t];
    __syncthreads();
    float acc = b_init[t];
    const float4* w = (const float4*)(W_init + t * E);
    const float4* x = (const float4*)sm;
#pragma unroll 8
    for (int e4 = 0; e4 < E / 4; e4++) {
        float4 a = w[e4], v = x[e4];
        acc = fmaf(a.x, v.x, acc); acc = fmaf(a.y, v.y, acc);
        acc = fmaf(a.z, v.z, acc); acc = fmaf(a.w, v.w, acc);
    }
    d_q1[b * E + t] = acc;
    d_q2[b * E + t] = acc;
    if (t == 0) {
        d_stopped[b] = 1; d_nol[b] = -1; d_ll[b] = 0.0f;
        d_expsum[b] = 0.0f;
    }
    if (t < 5) d_kl[b * 5 + t] = 0;
    if (t < 4) { d_ai[b * 4 + t] = 0; d_kr[b * 4 + t] = 0; }
}

// ---------------- bf16 MMA GEMM via ldmatrix: Kc8 = e4m3(h @ W^T) ----------------
// (unchanged from round 10)
__global__ void __launch_bounds__(256) gemm_kernel(const float* __restrict__ A) {
    __shared__ __nv_bfloat16 As[128][72];
    __shared__ __nv_bfloat16 Bs[64][136];
    const int t = threadIdx.x;
    const int warp = t >> 5, lane = t & 31;
    const int n0 = blockIdx.x * 64, m0 = blockIdx.y * 128;
    const int wm = (warp >> 1) * 32, wn = (warp & 1) * 32;

#pragma unroll
    for (int i = t; i < 64 * 16; i += 256) {
        int n = i >> 4, c8 = i & 15;
        *(uint4*)&Bs[n][c8 * 8] = *(const uint4*)(d_Wb + (size_t)(n0 + n) * 128 + c8 * 8);
    }

    float c[2][4][4];
#pragma unroll
    for (int i = 0; i < 2; i++)
#pragma unroll
        for (int j = 0; j < 4; j++)
#pragma unroll
            for (int k = 0; k < 4; k++) c[i][j][k] = 0.f;

    const int a_row = (lane & 15), a_colh = (lane >> 4) * 8;
    const int b_row = ((lane >> 4) & 1) * 8 + (lane & 7);
    const int b_colh = ((lane >> 3) & 1) * 8;

    unsigned a_addr0 = (unsigned)__cvta_generic_to_shared(&As[wm + a_row][a_colh]);
    unsigned a_addr1 = (unsigned)__cvta_generic_to_shared(&As[wm + 16 + a_row][a_colh]);
    unsigned b_addr0 = (unsigned)__cvta_generic_to_shared(&Bs[wn + b_row][b_colh]);
    unsigned b_addr1 = (unsigned)__cvta_generic_to_shared(&Bs[wn + 16 + b_row][b_colh]);

#pragma unroll
    for (int kh = 0; kh < 2; kh++) {
        __syncthreads();
#pragma unroll
        for (int i = t; i < 128 * 16; i += 256) {
            int row = i >> 4, c4 = i & 15;
            float4 v = *(const float4*)(A + (size_t)(m0 + row) * 128 + kh * 64 + c4 * 4);
            __nv_bfloat162 lo = __floats2bfloat162_rn(v.x, v.y);
            __nv_bfloat162 hi = __floats2bfloat162_rn(v.z, v.w);
            *(uint2*)&As[row][c4 * 4] = make_uint2(*(unsigned*)&lo, *(unsigned*)&hi);
        }
        __syncthreads();
#pragma unroll
        for (int ks = 0; ks < 4; ks++) {
            unsigned koff = ks * 32;
            unsigned bkoff = kh * 128 + ks * 32;
            unsigned af0[4], af1[4], bf0[4], bf1[4];
            LDSM4(af0, a_addr0 + koff);
            LDSM4(af1, a_addr1 + koff);
            LDSM4(bf0, b_addr0 + bkoff);
            LDSM4(bf1, b_addr1 + bkoff);
            MMA16816(c[0][0], af0, bf0[0], bf0[1]);
            MMA16816(c[0][1], af0, bf0[2], bf0[3]);
            MMA16816(c[0][2], af0, bf1[0], bf1[1]);
            MMA16816(c[0][3], af0, bf1[2], bf1[3]);
            MMA16816(c[1][0], af1, bf0[0], bf0[1]);
            MMA16816(c[1][1], af1, bf0[2], bf0[3]);
            MMA16816(c[1][2], af1, bf1[0], bf1[1]);
            MMA16816(c[1][3], af1, bf1[2], bf1[3]);
        }
    }

    const int qr = lane >> 2, qc = lane & 3;
#pragma unroll
    for (int mf = 0; mf < 2; mf++)
#pragma unroll
        for (int nf = 0; nf < 4; nf++) {
            int row = m0 + wm + mf * 16 + qr;
            int col = n0 + wn + nf * 8 + qc * 2;
            unsigned short p0 = fp8pack(c[mf][nf][0], c[mf][nf][1]);
            unsigned short p1 = fp8pack(c[mf][nf][2], c[mf][nf][3]);
            *(unsigned short*)(d_Kc8 + (size_t)row * 512 + col) = p0;
            *(unsigned short*)(d_Kc8 + (size_t)(row + 8) * 512 + col) = p1;
        }
}

// ---------------- fused GRU1+GRU2+Qproj (one block per b, 512 threads) ----------------
__global__ void __launch_bounds__(512) gruqproj_kernel(
    int iter, const float* __restrict__ h, const float* __restrict__ init_query,
    const float* __restrict__ Wih1, const float* __restrict__ Whh1,
    const float* __restrict__ bih1, const float* __restrict__ bhh1,
    const float* __restrict__ Wih2, const float* __restrict__ Whh2,
    const float* __restrict__ bih2, const float* __restrict__ bhh2,
    const float* __restrict__ WQ1, const float* __restrict__ WQ2,
    const float* __restrict__ WQ3, const float* __restrict__ WQ4) {
    int b = blockIdx.x, t = threadIdx.x;
    __shared__ __align__(16) float sx1[E], sx2[E], sh1[E], sh2[E], qf1[E], qf2[E];
    __shared__ float gi1[3 * E], gh1[3 * E], gi2[3 * E], gh2[3 * E];

    if (t < E) {
        float x1, x2;
        if (iter == 0) {
            x1 = init_query[t]; x2 = x1;
        } else {
            int act = d_act[b];
            x1 = h[((size_t)b * GS + act) * E + t];
            x2 = d_stopold_g[b] ? x1 : h[((size_t)b * GS + d_nolmod[b]) * E + t];
        }
        sx1[t] = x1; sx2[t] = x2;
        sh1[t] = d_q1[b * E + t]; sh2[t] = d_q2[b * E + t];
    }
    __syncthreads();

    // 768 row-tasks (384 per GRU), each = two 128-dots
    for (int task = t; task < 768; task += 512) {
        int gr = task >= 384 ? 1 : 0;
        int tt = task - gr * 384;
        const float* Wih = gr ? Wih2 : Wih1;
        const float* Whh = gr ? Whh2 : Whh1;
        float a = (gr ? bih2 : bih1)[tt];
        float cg = (gr ? bhh2 : bhh1)[tt];
        const float4* wi = (const float4*)(Wih + tt * E);
        const float4* wh = (const float4*)(Whh + tt * E);
        const float4* x4 = (const float4*)(gr ? sx2 : sx1);
        const float4* h4 = (const float4*)(gr ? sh2 : sh1);
#pragma unroll 8
        for (int e4 = 0; e4 < E / 4; e4++) {
            float4 wa = wi[e4], wb = wh[e4], xv = x4[e4], hv = h4[e4];
            a = fmaf(wa.x, xv.x, a); a = fmaf(wa.y, xv.y, a);
            a = fmaf(wa.z, xv.z, a); a = fmaf(wa.w, xv.w, a);
            cg = fmaf(wb.x, hv.x, cg); cg = fmaf(wb.y, hv.y, cg);
            cg = fmaf(wb.z, hv.z, cg); cg = fmaf(wb.w, hv.w, cg);
        }
        if (gr) { gi2[tt] = a; gh2[tt] = cg; }
        else    { gi1[tt] = a; gh1[tt] = cg; }
    }
    __syncthreads();

    if (t < 2 * E) {
        int gr = t >> 7, tt = t & 127;
        const float* gi = gr ? gi2 : gi1;
        const float* gh = gr ? gh2 : gh1;
        const float* shh = gr ? sh2 : sh1;
        float rr = sigmoidf_(gi[tt] + gh[tt]);
        float z  = sigmoidf_(gi[E + tt] + gh[E + tt]);
        float n  = tanhf(gi[2 * E + tt] + rr * gh[2 * E + tt]);
        float qv = (1.0f - z) * n + z * shh[tt];
        if (gr) { d_q2[b * E + tt] = qv; qf2[tt] = qv; }
        else    { d_q1[b * E + tt] = qv; qf1[tt] = qv; }
    }
    __syncthreads();

    // Q projections (512 dots)
    {
        int j = t >> 7, f = t & 127;
        const float* W = (j == 0) ? WQ1 : (j == 1) ? WQ2 : (j == 2) ? WQ3 : WQ4;
        const float4* w = (const float4*)(W + f * E);
        const float4* x = (const float4*)((j == 0 || j == 2) ? qf1 : qf2);
        float acc = 0.f;
#pragma unroll 8
        for (int e4 = 0; e4 < E / 4; e4++) {
            float4 a = w[e4], v = x[e4];
            acc = fmaf(a.x, v.x, acc); acc = fmaf(a.y, v.y, acc);
            acc = fmaf(a.z, v.z, acc); acc = fmaf(a.w, v.w, acc);
        }
        d_Qp[b * 512 + t] = acc;
    }
}

// ---------------- score (logits + inline mask + expsum + logit-at-action) ----------------
__global__ void __launch_bounds__(256) score_kernel(int iter, const int* __restrict__ last_action,
                                                    const int* __restrict__ fixed_action,
                                                    const float* __restrict__ V1,
                                                    const float* __restrict__ V2) {
    int b = blockIdx.x, t = threadIdx.x;
    int warp = t >> 5, lane = t & 31;
    __shared__ float sQ[512];
    __shared__ float sV[256];
    __shared__ float sE[8];
    sQ[t] = d_Qp[b * 512 + t];
    sQ[256 + t] = d_Qp[b * 512 + 256 + t];
    sV[t] = (t < 128) ? V1[t] : V2[t - 128];
    __syncthreads();

    int g = blockIdx.y * 8 + warp;
    const unsigned char* __restrict__ Kc = d_Kc8 + ((size_t)b * GS + g) * 512;
    int f0 = lane * 4;
    unsigned u1 = *(const unsigned*)(Kc + f0);
    unsigned u2 = *(const unsigned*)(Kc + 128 + f0);
    unsigned u3 = *(const unsigned*)(Kc + 256 + f0);
    unsigned u4 = *(const unsigned*)(Kc + 384 + f0);
    float k1[4], k2[4], k3[4], k4[4];
    fp8x4_to_f32(u1, k1); fp8x4_to_f32(u2, k2);
    fp8x4_to_f32(u3, k3); fp8x4_to_f32(u4, k4);
    float s = 0.f;
#pragma unroll
    for (int i = 0; i < 4; i++) {
        int f = f0 + i;
        float a1 = fmaf(k3[i], sQ[256 + f], k1[i] + sQ[f]);
        float a2 = fmaf(k4[i], sQ[384 + f], k2[i] + sQ[128 + f]);
        s = fmaf(sV[f], tanh_fast(a1), s);
        s = fmaf(sV[128 + f], tanh_fast(a2), s);
    }
#pragma unroll
    for (int o = 16; o; o >>= 1) s += __shfl_xor_sync(0xFFFFFFFFu, s, o);

    if (lane == 0) {
        // inline mask from prev update's scalars
        bool m;
        if (iter == 0) {
            m = (g == last_action[b]);
        } else {
            int v = d_vtt[b * GS + g];
            m = (v <= d_va[b]);
            if (iter == 1) m = m || (v > GS - 2);
            if (d_stopnew[b] && g == d_act[b]) m = false;
            if (d_allow[b] && g == d_ai0g[b]) m = false;
        }
        float lgt = tanhf(s) * CLIPV;
        int act = (iter == 0) ? fixed_action[b * KM] : d_nextact[b];
        if (g == act) d_logact[b] = m ? NEGV : lgt;
        sE[warp] = m ? 0.0f : expf(lgt - CLIPV);   // shifted by clip bound
    }
    __syncthreads();
    if (t == 0) {
        float e = sE[0];
#pragma unroll
        for (int i = 1; i < 8; i++) e += sE[i];
        atomicAdd(&d_expsum[b], e);
    }
}

// ---------------- scalar bookkeeping update (one thread per b) ----------------
__global__ void update_kernel(int iter, const int* __restrict__ rec,
                              const int* __restrict__ fixed_action) {
    int b = threadIdx.x;          // <<<1,128>>>
    if (b >= BS) return;
    const int bG = b * GS;

    int stop_old = d_stopped[b];
    int nol_old  = d_nol[b];
    int ai0_old  = d_ai[b * 4];
    int action   = (iter == 0) ? fixed_action[b * KM] : d_nextact[b];

    // expsum == 0 exactly <=> ALL logits masked -> logp[action] = -log(GS)
    float es = d_expsum[b];
    float loss = (es > 0.0f) ? (d_logact[b] - (CLIPV + logf(es)))
                             : (-logf((float)GS));
    if (iter == 0 || !stop_old) d_ll[b] += loss;

    int nna = rec[bG + action];
    d_ai[b * 4 + iter] = action;
    if (stop_old) d_kl[b * 5 + iter] = action;
    int krm1 = ((iter - 1) + KM) % KM;
    if (!stop_old) d_kr[b * 4 + krm1] = action;
    d_kl[b * 5 + iter + 1] = nna;

    int eq = (action == nol_old) ? 1 : 0;
    int stop_new = (iter == 0) ? eq : (stop_old | eq);
    if (stop_new) {
        int klm1 = ((iter - 1) + 5) % 5;
        d_kl[b * 5 + iter] = d_kl[b * 5 + klm1];
        d_kr[b * 4 + iter] = d_kr[b * 4 + krm1];
    }
    d_stopped[b] = stop_new;
    d_nol[b] = stop_new ? -1 : nna;

    int ai0 = (iter == 0) ? action : ai0_old;

    // handoff scalars for iter+1
    d_act[b] = action;
    d_stopold_g[b] = stop_old;
    d_nolmod[b] = ((nol_old % GS) + GS) % GS;   // Python floored mod
    d_va[b] = d_vtt[bG + action];
    d_stopnew[b] = stop_new;
    d_ai0g[b] = ai0;
    d_allow[b] = (!stop_new && nna == ai0) ? 1 : 0;
    d_nextact[b] = (iter < KM - 1)
                   ? (stop_new ? ai0 : fixed_action[b * KM + iter + 1]) : 0;
    d_expsum[b] = 0.0f;
}

// ---------------- output ----------------
__global__ void out_kernel(float* __restrict__ out) {
    int idx = blockIdx.x * 256 + threadIdx.x;
    if (idx < BS * 12) {
        int b = idx / 12, j = idx % 12;
        int v;
        if (j < 4) v = d_ai[b * 4 + j];
        else if (j < 8) v = d_kl[b * 5 + (j - 4)];
        else {
            int jj = j - 8;
            if (jj == 3 && !d_stopped[b]) v = d_kl[b * 5 + 4];  // post-loop kr fix
            else v = d_kr[b * 4 + jj];
        }
        out[idx] = (float)v;
    } else if (idx < BS * 12 + BS) {
        out[idx] = d_ll[idx - BS * 12];
    }
}

// ---------------- launch ----------------
extern "C" void kernel_launch(void* const* d_in, const int* in_sizes, int n_in,
                              void* d_out, int out_size) {
    (void)in_sizes; (void)n_in; (void)out_size;
    const float* h            = (const float*)d_in[0];
    const int*   rec          = (const int*)  d_in[1];
    /* context2 d_in[2] unused */
    const int*   visited_time = (const int*)  d_in[3];
    const int*   last_action  = (const int*)  d_in[4];
    const int*   fixed_action = (const int*)  d_in[5];
    const float* W_K1 = (const float*)d_in[6];
    const float* W_K2 = (const float*)d_in[7];
    const float* W_K3 = (const float*)d_in[8];
    const float* W_K4 = (const float*)d_in[9];
    const float* W_Q1 = (const float*)d_in[10];
    const float* W_Q2 = (const float*)d_in[11];
    const float* W_Q3 = (const float*)d_in[12];
    const float* W_Q4 = (const float*)d_in[13];
    const float* W_init     = (const float*)d_in[14];
    const float* b_init     = (const float*)d_in[15];
    const float* V1         = (const float*)d_in[16];
    const float* V2         = (const float*)d_in[17];
    const float* init_query = (const float*)d_in[18];
    const float* r1_Wih = (const float*)d_in[19];
    const float* r1_Whh = (const float*)d_in[20];
    const float* r1_bih = (const float*)d_in[21];
    const float* r1_bhh = (const float*)d_in[22];
    const float* r2_Wih = (const float*)d_in[23];
    const float* r2_Whh = (const float*)d_in[24];
    const float* r2_bih = (const float*)d_in[25];
    const float* r2_bhh = (const float*)d_in[26];

    convert_w<<<256, 256>>>(W_K1, W_K2, W_K3, W_K4);
    hmean_kernel<<<BS, 512>>>(h);
    vtt_kernel<<<BS, 256>>>(visited_time, fixed_action);
    init_kernel<<<BS, 128>>>(W_init, b_init, init_query);
    gemm_kernel<<<dim3(8, 2000), 256>>>(h);   // n fastest -> A tile L2 reuse

    for (int i = 0; i < KM; i++) {
        gruqproj_kernel<<<BS, 512>>>(i, h, init_query,
                                     r1_Wih, r1_Whh, r1_bih, r1_bhh,
                                     r2_Wih, r2_Whh, r2_bih, r2_bhh,
                                     W_Q1, W_Q2, W_Q3, W_Q4);
        score_kernel<<<dim3(BS, 250), 256>>>(i, last_action, fixed_action, V1, V2);
        update_kernel<<<1, 128>>>(i, rec, fixed_action);
    }
    out_kernel<<<7, 256>>>((float*)d_out);
}

// round 12
// speedup vs baseline: 1.8475x; 1.8475x over previous
#include <cuda_runtime.h>
#include <cuda_bf16.h>
#include <cuda_fp16.h>
#include <math.h>
#include <stdint.h>

#define BS   128
#define GS   2000
#define E    128
#define KM   4
#define NEGV (-1.0e30f)
#define CLIPV 10.0f

// ---------------- device scratch (static globals; no runtime allocation) ----------------
__device__ unsigned char d_Kc8[(size_t)BS * GS * 512];  // [b][g][K1|K2|K3|K4] e4m3 (131 MB)
__device__ __nv_bfloat16 d_Wb[512 * 128];               // [n=j*128+f][k=e] bf16 (col-major B)
__device__ __nv_bfloat16 d_Wgb[4 * 384 * 128];          // r1_Wih|r1_Whh|r2_Wih|r2_Whh bf16
__device__ __nv_bfloat16 d_WQb[4 * 128 * 128];          // WQ1..WQ4 bf16
__device__ float d_logits[BS * GS];
__device__ float d_expsum[BS];
__device__ unsigned char d_mask[BS * GS];
__device__ int   d_vtt[BS * GS];
__device__ float d_q1[BS * E], d_q2[BS * E];
__device__ float d_iq1[BS * E], d_iq2[BS * E];
__device__ float d_Qp[BS * 512];                        // [Q1|Q2|Q3|Q4] per b
__device__ float d_hmean[BS * E];
__device__ int   d_ai[BS * 4];
__device__ int   d_kl[BS * 5];
__device__ int   d_kr[BS * 4];
__device__ int   d_nol[BS];
__device__ int   d_stopped[BS];
__device__ float d_ll[BS];

// ---------------- math helpers ----------------
__device__ __forceinline__ float fast_rcp(float x) {
    float r = __uint_as_float(0x7EF311C3u - __float_as_uint(x));
    r = r * (2.0f - x * r);
    r = r * (2.0f - x * r);
    return r;
}
__device__ __forceinline__ float tanh_fast(float x) {
    // Pade(5,4), clamp 3.6; abs err <= ~1e-3; fma/alu pipes only
    float xc = fminf(fmaxf(x, -3.6f), 3.6f);
    float x2 = xc * xc;
    float num = xc * fmaf(x2, x2 + 105.0f, 945.0f);
    float den = fmaf(x2, fmaf(15.0f, x2, 420.0f), 945.0f);
    return num * fast_rcp(den);
}
__device__ __forceinline__ float sigmoidf_(float x) { return 1.0f / (1.0f + expf(-x)); }

// pack two f32 -> e4m3x2 (byte0 = a, byte1 = b)
__device__ __forceinline__ unsigned short fp8pack(float a, float b) {
    unsigned short p;
    asm("cvt.rn.satfinite.e4m3x2.f32 %0, %1, %2;" : "=h"(p) : "f"(b), "f"(a));
    return p;
}
// 4 e4m3 bytes -> 4 floats (o[0] = byte0 ...)
__device__ __forceinline__ void fp8x4_to_f32(unsigned u, float* o) {
    unsigned h01, h23;
    asm("{\n\t.reg .b16 lo, hi;\n\t"
        "mov.b32 {lo, hi}, %2;\n\t"
        "cvt.rn.f16x2.e4m3x2 %0, lo;\n\t"
        "cvt.rn.f16x2.e4m3x2 %1, hi;\n\t}"
        : "=r"(h01), "=r"(h23) : "r"(u));
    float2 x = __half22float2(*reinterpret_cast<__half2*>(&h01));
    float2 y = __half22float2(*reinterpret_cast<__half2*>(&h23));
    o[0] = x.x; o[1] = x.y; o[2] = y.x; o[3] = y.y;
}
__device__ __forceinline__ float2 bf2f(unsigned u) {
    return __bfloat1622float2(*reinterpret_cast<__nv_bfloat162*>(&u));
}

#define LDSM4(r, addr) \
    asm volatile("ldmatrix.sync.aligned.m8n8.x4.shared.b16 {%0,%1,%2,%3}, [%4];" \
                 : "=r"((r)[0]), "=r"((r)[1]), "=r"((r)[2]), "=r"((r)[3]) : "r"(addr))

#define MMA16816(c, a, b0, b1) \
    asm volatile("mma.sync.aligned.m16n8k16.row.col.f32.bf16.bf16.f32 " \
                 "{%0,%1,%2,%3},{%4,%5,%6,%7},{%8,%9},{%0,%1,%2,%3};" \
                 : "+f"((c)[0]), "+f"((c)[1]), "+f"((c)[2]), "+f"((c)[3]) \
                 : "r"((a)[0]), "r"((a)[1]), "r"((a)[2]), "r"((a)[3]), "r"(b0), "r"(b1))

// bf16 dot-8 helper: wa/wb = uint4 of 8 bf16; x4 points at 8 smem floats
#define DOT8(acc, w4, xp)                                            \
    do {                                                             \
        float2 _p; float4 _x0 = (xp)[0], _x1 = (xp)[1];              \
        _p = bf2f((w4).x); acc = fmaf(_p.x, _x0.x, acc); acc = fmaf(_p.y, _x0.y, acc); \
        _p = bf2f((w4).y); acc = fmaf(_p.x, _x0.z, acc); acc = fmaf(_p.y, _x0.w, acc); \
        _p = bf2f((w4).z); acc = fmaf(_p.x, _x1.x, acc); acc = fmaf(_p.y, _x1.y, acc); \
        _p = bf2f((w4).w); acc = fmaf(_p.x, _x1.z, acc); acc = fmaf(_p.y, _x1.w, acc); \
    } while (0)

// ---------------- setup kernels ----------------
__global__ void convert_w(const float* __restrict__ W1, const float* __restrict__ W2,
                          const float* __restrict__ W3, const float* __restrict__ W4) {
    int idx = blockIdx.x * blockDim.x + threadIdx.x;    // 65536
    if (idx >= 512 * 128) return;
    int j = idx >> 14, r = idx & 16383;
    const float* W = (j == 0) ? W1 : (j == 1) ? W2 : (j == 2) ? W3 : W4;
    d_Wb[idx] = __float2bfloat16(W[r]);
}

__global__ void convert_wsmall(const float* __restrict__ g0, const float* __restrict__ g1,
                               const float* __restrict__ g2, const float* __restrict__ g3,
                               const float* __restrict__ q0, const float* __restrict__ q1,
                               const float* __restrict__ q2, const float* __restrict__ q3) {
    int idx = blockIdx.x * blockDim.x + threadIdx.x;    // 262144 total
    if (idx < 4 * 49152) {
        int m = idx / 49152, r = idx % 49152;
        const float* W = (m == 0) ? g0 : (m == 1) ? g1 : (m == 2) ? g2 : g3;
        d_Wgb[idx] = __float2bfloat16(W[r]);
    } else if (idx < 4 * 49152 + 4 * 16384) {
        int k = idx - 4 * 49152;
        int m = k / 16384, r = k % 16384;
        const float* W = (m == 0) ? q0 : (m == 1) ? q1 : (m == 2) ? q2 : q3;
        d_WQb[k] = __float2bfloat16(W[r]);
    }
}

__global__ void hmean_kernel(const float* __restrict__ h) {
    int b = blockIdx.x, t = threadIdx.x;                 // 512 threads
    int e = t & 127, q = t >> 7;
    __shared__ float part[4][128];
    float s = 0.f;
    for (int g = q * 500; g < (q + 1) * 500; g++)
        s += h[((size_t)b * GS + g) * E + e];
    part[q][e] = s;
    __syncthreads();
    if (t < 128)
        d_hmean[b * E + t] = (part[0][t] + part[1][t] + part[2][t] + part[3][t]) * (1.0f / GS);
}

__global__ void init_kernel(const float* __restrict__ W_init, const float* __restrict__ b_init,
                            const float* __restrict__ init_query) {
    int b = blockIdx.x, t = threadIdx.x;                 // 128 threads
    __shared__ __align__(16) float sm[E];
    sm[t] = d_hmean[b * E + t];
    __syncthreads();
    float acc = b_init[t];
    const float4* w = (const float4*)(W_init + t * E);
    const float4* x = (const float4*)sm;
#pragma unroll 8
    for (int e4 = 0; e4 < E / 4; e4++) {
        float4 a = w[e4], v = x[e4];
        acc = fmaf(a.x, v.x, acc); acc = fmaf(a.y, v.y, acc);
        acc = fmaf(a.z, v.z, acc); acc = fmaf(a.w, v.w, acc);
    }
    d_q1[b * E + t] = acc;
    d_q2[b * E + t] = acc;
    float iq = init_query[t];
    d_iq1[b * E + t] = iq;
    d_iq2[b * E + t] = iq;
    if (t == 0) { d_stopped[b] = 1; d_nol[b] = -1; d_ll[b] = 0.0f; }
    if (t < 5) d_kl[b * 5 + t] = 0;
    if (t < 4) { d_ai[b * 4 + t] = 0; d_kr[b * 4 + t] = 0; }
}

// ---------------- bf16 MMA GEMM via ldmatrix: Kc8 = e4m3(h @ W^T) ----------------
// (unchanged from round 10)
__global__ void __launch_bounds__(256) gemm_kernel(const float* __restrict__ A) {
    __shared__ __nv_bfloat16 As[128][72];
    __shared__ __nv_bfloat16 Bs[64][136];
    const int t = threadIdx.x;
    const int warp = t >> 5, lane = t & 31;
    const int n0 = blockIdx.x * 64, m0 = blockIdx.y * 128;
    const int wm = (warp >> 1) * 32, wn = (warp & 1) * 32;

#pragma unroll
    for (int i = t; i < 64 * 16; i += 256) {
        int n = i >> 4, c8 = i & 15;
        *(uint4*)&Bs[n][c8 * 8] = *(const uint4*)(d_Wb + (size_t)(n0 + n) * 128 + c8 * 8);
    }

    float c[2][4][4];
#pragma unroll
    for (int i = 0; i < 2; i++)
#pragma unroll
        for (int j = 0; j < 4; j++)
#pragma unroll
            for (int k = 0; k < 4; k++) c[i][j][k] = 0.f;

    const int a_row = (lane & 15), a_colh = (lane >> 4) * 8;
    const int b_row = ((lane >> 4) & 1) * 8 + (lane & 7);
    const int b_colh = ((lane >> 3) & 1) * 8;

    unsigned a_addr0 = (unsigned)__cvta_generic_to_shared(&As[wm + a_row][a_colh]);
    unsigned a_addr1 = (unsigned)__cvta_generic_to_shared(&As[wm + 16 + a_row][a_colh]);
    unsigned b_addr0 = (unsigned)__cvta_generic_to_shared(&Bs[wn + b_row][b_colh]);
    unsigned b_addr1 = (unsigned)__cvta_generic_to_shared(&Bs[wn + 16 + b_row][b_colh]);

#pragma unroll
    for (int kh = 0; kh < 2; kh++) {
        __syncthreads();
#pragma unroll
        for (int i = t; i < 128 * 16; i += 256) {
            int row = i >> 4, c4 = i & 15;
            float4 v = *(const float4*)(A + (size_t)(m0 + row) * 128 + kh * 64 + c4 * 4);
            __nv_bfloat162 lo = __floats2bfloat162_rn(v.x, v.y);
            __nv_bfloat162 hi = __floats2bfloat162_rn(v.z, v.w);
            *(uint2*)&As[row][c4 * 4] = make_uint2(*(unsigned*)&lo, *(unsigned*)&hi);
        }
        __syncthreads();
#pragma unroll
        for (int ks = 0; ks < 4; ks++) {
            unsigned koff = ks * 32;
            unsigned bkoff = kh * 128 + ks * 32;
            unsigned af0[4], af1[4], bf0[4], bf1[4];
            LDSM4(af0, a_addr0 + koff);
            LDSM4(af1, a_addr1 + koff);
            LDSM4(bf0, b_addr0 + bkoff);
            LDSM4(bf1, b_addr1 + bkoff);
            MMA16816(c[0][0], af0, bf0[0], bf0[1]);
            MMA16816(c[0][1], af0, bf0[2], bf0[3]);
            MMA16816(c[0][2], af0, bf1[0], bf1[1]);
            MMA16816(c[0][3], af0, bf1[2], bf1[3]);
            MMA16816(c[1][0], af1, bf0[0], bf0[1]);
            MMA16816(c[1][1], af1, bf0[2], bf0[3]);
            MMA16816(c[1][2], af1, bf1[0], bf1[1]);
            MMA16816(c[1][3], af1, bf1[2], bf1[3]);
        }
    }

    const int qr = lane >> 2, qc = lane & 3;
#pragma unroll
    for (int mf = 0; mf < 2; mf++)
#pragma unroll
        for (int nf = 0; nf < 4; nf++) {
            int row = m0 + wm + mf * 16 + qr;
            int col = n0 + wn + nf * 8 + qc * 2;
            unsigned short p0 = fp8pack(c[mf][nf][0], c[mf][nf][1]);
            unsigned short p1 = fp8pack(c[mf][nf][2], c[mf][nf][3]);
            *(unsigned short*)(d_Kc8 + (size_t)row * 512 + col) = p0;
            *(unsigned short*)(d_Kc8 + (size_t)(row + 8) * 512 + col) = p1;
        }
}

// ---------------- per-iteration kernels ----------------
__global__ void gru_kernel(const float* __restrict__ bih1, const float* __restrict__ bhh1,
                           const float* __restrict__ bih2, const float* __restrict__ bhh2) {
    int b = blockIdx.x, r = blockIdx.y, t = threadIdx.x;   // 384 threads
    const float* bih = r ? bih2 : bih1;
    const float* bhh = r ? bhh2 : bhh1;
    float* q = r ? d_q2 : d_q1;
    const float* iq = r ? d_iq2 : d_iq1;

    __shared__ __align__(16) float sx[E], sh[E];
    __shared__ float gi[3 * E], gh[3 * E];
    if (t < E) { sx[t] = iq[b * E + t]; sh[t] = q[b * E + t]; }
    __syncthreads();

    float a = bih[t], cgh = bhh[t];
    const uint4* wi = (const uint4*)(d_Wgb + ((size_t)(r * 2) * 384 + t) * 128);
    const uint4* wh = (const uint4*)(d_Wgb + ((size_t)(r * 2 + 1) * 384 + t) * 128);
    const float4* x4 = (const float4*)sx;
    const float4* h4 = (const float4*)sh;
#pragma unroll 4
    for (int e8 = 0; e8 < E / 8; e8++) {
        uint4 wa = wi[e8], wb = wh[e8];
        DOT8(a, wa, x4 + e8 * 2);
        DOT8(cgh, wb, h4 + e8 * 2);
    }
    gi[t] = a; gh[t] = cgh;
    __syncthreads();
    if (t < E) {
        float rr = sigmoidf_(gi[t] + gh[t]);
        float z  = sigmoidf_(gi[E + t] + gh[E + t]);
        float n  = tanhf(gi[2 * E + t] + rr * gh[2 * E + t]);
        q[b * E + t] = (1.0f - z) * n + z * sh[t];
    }
}

__global__ void qproj_kernel() {
    int b = blockIdx.x, t = threadIdx.x;                    // 512 threads
    __shared__ __align__(16) float s1[E], s2[E];
    if (t < E) s1[t] = d_q1[b * E + t];
    else if (t < 2 * E) s2[t - E] = d_q2[b * E + t - E];
    if (t == 0) d_expsum[b] = 0.0f;    // reset for this iteration's score pass
    __syncthreads();
    int j = t >> 7, f = t & 127;
    const uint4* w = (const uint4*)(d_WQb + ((size_t)j * 128 + f) * 128);
    const float4* x = (const float4*)((j == 0 || j == 2) ? s1 : s2);
    float acc = 0.f;
#pragma unroll 4
    for (int e8 = 0; e8 < E / 8; e8++) {
        uint4 wa = w[e8];
        DOT8(acc, wa, x + e8 * 2);
    }
    d_Qp[b * 512 + t] = acc;
}

// 2 g-rows per warp: grid (BS, 125), 256 threads -> 16 rows per block
__global__ void __launch_bounds__(256) score_kernel(int iter, const int* __restrict__ last_action,
                                                    const float* __restrict__ V1,
                                                    const float* __restrict__ V2) {
    int b = blockIdx.x, t = threadIdx.x;
    int warp = t >> 5, lane = t & 31;
    __shared__ float sQ[512];
    __shared__ float sV[256];
    __shared__ float sE[8];
    sQ[t] = d_Qp[b * 512 + t];
    sQ[256 + t] = d_Qp[b * 512 + 256 + t];
    sV[t] = (t < 128) ? V1[t] : V2[t - 128];
    __syncthreads();

    int g0 = blockIdx.y * 16 + warp * 2;
    const unsigned char* __restrict__ Kc = d_Kc8 + ((size_t)b * GS + g0) * 512;
    int f0 = lane * 4;
    // issue all 8 row loads up front (MLP)
    unsigned a1 = *(const unsigned*)(Kc + f0);
    unsigned a2 = *(const unsigned*)(Kc + 128 + f0);
    unsigned a3 = *(const unsigned*)(Kc + 256 + f0);
    unsigned a4 = *(const unsigned*)(Kc + 384 + f0);
    unsigned b1 = *(const unsigned*)(Kc + 512 + f0);
    unsigned b2 = *(const unsigned*)(Kc + 640 + f0);
    unsigned b3 = *(const unsigned*)(Kc + 768 + f0);
    unsigned b4 = *(const unsigned*)(Kc + 896 + f0);

    float k1[4], k2[4], k3[4], k4[4];
    float s0 = 0.f, s1 = 0.f;
    fp8x4_to_f32(a1, k1); fp8x4_to_f32(a2, k2);
    fp8x4_to_f32(a3, k3); fp8x4_to_f32(a4, k4);
#pragma unroll
    for (int i = 0; i < 4; i++) {
        int f = f0 + i;
        float v1 = fmaf(k3[i], sQ[256 + f], k1[i] + sQ[f]);
        float v2 = fmaf(k4[i], sQ[384 + f], k2[i] + sQ[128 + f]);
        s0 = fmaf(sV[f], tanh_fast(v1), s0);
        s0 = fmaf(sV[128 + f], tanh_fast(v2), s0);
    }
    fp8x4_to_f32(b1, k1); fp8x4_to_f32(b2, k2);
    fp8x4_to_f32(b3, k3); fp8x4_to_f32(b4, k4);
#pragma unroll
    for (int i = 0; i < 4; i++) {
        int f = f0 + i;
        float v1 = fmaf(k3[i], sQ[256 + f], k1[i] + sQ[f]);
        float v2 = fmaf(k4[i], sQ[384 + f], k2[i] + sQ[128 + f]);
        s1 = fmaf(sV[f], tanh_fast(v1), s1);
        s1 = fmaf(sV[128 + f], tanh_fast(v2), s1);
    }
#pragma unroll
    for (int o = 16; o; o >>= 1) {
        s0 += __shfl_xor_sync(0xFFFFFFFFu, s0, o);
        s1 += __shfl_xor_sync(0xFFFFFFFFu, s1, o);
    }
    if (lane == 0) {
        float lg0 = tanhf(s0) * CLIPV;
        float lg1 = tanhf(s1) * CLIPV;
        bool m0, m1;
        if (iter == 0) {
            int la = last_action[b];
            m0 = (g0 == la); m1 = (g0 + 1 == la);
        } else {
            m0 = d_mask[b * GS + g0] != 0;
            m1 = d_mask[b * GS + g0 + 1] != 0;
        }
        d_logits[b * GS + g0] = m0 ? NEGV : lg0;
        d_logits[b * GS + g0 + 1] = m1 ? NEGV : lg1;
        float e0 = m0 ? 0.0f : expf(lg0 - CLIPV);
        float e1 = m1 ? 0.0f : expf(lg1 - CLIPV);
        sE[warp] = e0 + e1;
    }
    __syncthreads();
    if (t == 0) {
        float e = sE[0];
#pragma unroll
        for (int i = 1; i < 8; i++) e += sE[i];
        atomicAdd(&d_expsum[b], e);
    }
}

__global__ void __launch_bounds__(256) update_kernel(int iter, const int* __restrict__ rec,
                                                     const int* __restrict__ vt,
                                                     const float* __restrict__ h,
                                                     const int* __restrict__ fixed_action) {
    int b = blockIdx.x, t = threadIdx.x;   // 256 threads, one block per b
    __shared__ int s_action, s_stopold, s_stopnew, s_nolmod, s_allow, s_ai0;

    const int bG = b * GS;

    if (t == 0) {
        int stop_old = d_stopped[b];
        int nol_old  = d_nol[b];
        int ai0_old  = d_ai[b * 4];
        int action   = (iter > 0 && stop_old) ? ai0_old : fixed_action[b * KM + iter];

        // expsum == 0 exactly <=> ALL logits masked. Reference's shifted
        // log-softmax gives logp[action] = -log(GS) in that case.
        float es = d_expsum[b];
        float loss = (es > 0.0f) ? (d_logits[bG + action] - (CLIPV + logf(es)))
                                 : (-logf((float)GS));
        if (iter == 0) d_ll[b] += loss;
        else if (!stop_old) d_ll[b] += loss;

        int nna = rec[bG + action];
        d_ai[b * 4 + iter] = action;
        if (stop_old) d_kl[b * 5 + iter] = action;
        int krm1 = ((iter - 1) + KM) % KM;
        if (!stop_old) d_kr[b * 4 + krm1] = action;
        d_kl[b * 5 + iter + 1] = nna;

        int eq = (action == nol_old) ? 1 : 0;
        int stop_new = (iter == 0) ? eq : (stop_old | eq);
        if (stop_new) {
            int klm1 = ((iter - 1) + 5) % 5;
            d_kl[b * 5 + iter] = d_kl[b * 5 + klm1];
            d_kr[b * 4 + iter] = d_kr[b * 4 + krm1];
        }
        d_stopped[b] = stop_new;
        d_nol[b] = stop_new ? -1 : nna;

        int ai0 = (iter == 0) ? action : ai0_old;
        s_action = action;
        s_stopold = stop_old;
        s_stopnew = stop_new;
        s_nolmod = ((nol_old % GS) + GS) % GS;   // Python floored mod
        s_ai0 = ai0;
        s_allow = (!stop_new && nna == ai0) ? 1 : 0;
    }
    __syncthreads();

    int act = s_action;
    int va = (iter == 0) ? 0 : d_vtt[bG + act];
    int vta = (iter == 0) ? vt[bG + act] : 0;
    for (int g = t; g < GS; g += 256) {
        int v;
        if (iter == 0) {
            v = (((vt[bG + g] - vta) % GS) + GS) % GS;
            d_vtt[bG + g] = v;
        } else {
            v = d_vtt[bG + g];
        }
        bool m = (v <= va);
        if (iter == 0) m = m || (v > GS - 2);
        if (s_stopnew && g == act) m = false;
        if (s_allow && g == s_ai0) m = false;
        d_mask[bG + g] = m ? 1 : 0;
    }

    if (t < E) {
        float hq1 = h[((size_t)bG + act) * E + t];
        d_iq1[b * E + t] = hq1;
        d_iq2[b * E + t] = s_stopold ? hq1 : h[((size_t)bG + s_nolmod) * E + t];
    }
}

// ---------------- output ----------------
__global__ void out_kernel(float* __restrict__ out) {
    int idx = blockIdx.x * 256 + threadIdx.x;
    if (idx < BS * 12) {
        int b = idx / 12, j = idx % 12;
        int v;
        if (j < 4) v = d_ai[b * 4 + j];
        else if (j < 8) v = d_kl[b * 5 + (j - 4)];
        else {
            int jj = j - 8;
            if (jj == 3 && !d_stopped[b]) v = d_kl[b * 5 + 4];  // post-loop kr fix
            else v = d_kr[b * 4 + jj];
        }
        out[idx] = (float)v;
    } else if (idx < BS * 12 + BS) {
        out[idx] = d_ll[idx - BS * 12];
    }
}

// ---------------- launch ----------------
extern "C" void kernel_launch(void* const* d_in, const int* in_sizes, int n_in,
                              void* d_out, int out_size) {
    (void)in_sizes; (void)n_in; (void)out_size;
    const float* h            = (const float*)d_in[0];
    const int*   rec          = (const int*)  d_in[1];
    /* context2 d_in[2] unused */
    const int*   visited_time = (const int*)  d_in[3];
    const int*   last_action  = (const int*)  d_in[4];
    const int*   fixed_action = (const int*)  d_in[5];
    const float* W_K1 = (const float*)d_in[6];
    const float* W_K2 = (const float*)d_in[7];
    const float* W_K3 = (const float*)d_in[8];
    const float* W_K4 = (const float*)d_in[9];
    const float* W_Q1 = (const float*)d_in[10];
    const float* W_Q2 = (const float*)d_in[11];
    const float* W_Q3 = (const float*)d_in[12];
    const float* W_Q4 = (const float*)d_in[13];
    const float* W_init     = (const float*)d_in[14];
    const float* b_init     = (const float*)d_in[15];
    const float* V1         = (const float*)d_in[16];
    const float* V2         = (const float*)d_in[17];
    const float* init_query = (const float*)d_in[18];
    const float* r1_Wih = (const float*)d_in[19];
    const float* r1_Whh = (const float*)d_in[20];
    const float* r1_bih = (const float*)d_in[21];
    const float* r1_bhh = (const float*)d_in[22];
    const float* r2_Wih = (const float*)d_in[23];
    const float* r2_Whh = (const float*)d_in[24];
    const float* r2_bih = (const float*)d_in[25];
    const float* r2_bhh = (const float*)d_in[26];

    convert_w<<<256, 256>>>(W_K1, W_K2, W_K3, W_K4);
    convert_wsmall<<<1024, 256>>>(r1_Wih, r1_Whh, r2_Wih, r2_Whh,
                                  W_Q1, W_Q2, W_Q3, W_Q4);
    hmean_kernel<<<BS, 512>>>(h);
    init_kernel<<<BS, 128>>>(W_init, b_init, init_query);
    gemm_kernel<<<dim3(8, 2000), 256>>>(h);   // n fastest -> A tile L2 reuse

    for (int i = 0; i < KM; i++) {
        gru_kernel<<<dim3(BS, 2), 384>>>(r1_bih, r1_bhh, r2_bih, r2_bhh);
        qproj_kernel<<<BS, 512>>>();
        score_kernel<<<dim3(BS, 125), 256>>>(i, last_action, V1, V2);
        update_kernel<<<BS, 256>>>(i, rec, visited_time, h, fixed_action);
    }
    out_kernel<<<7, 256>>>((float*)d_out);
}

// round 13
// speedup vs baseline: 1.9649x; 1.0635x over previous
#include <cuda_runtime.h>
#include <cuda_bf16.h>
#include <cuda_fp16.h>
#include <math.h>
#include <stdint.h>

#define BS   128
#define GS   2000
#define E    128
#define KM   4
#define NEGV (-1.0e30f)
#define CLIPV 10.0f

// ---------------- device scratch (static globals; no runtime allocation) ----------------
__device__ unsigned char d_Kc8[(size_t)BS * GS * 512];  // [b][g][K1|K2|K3|K4] e4m3 (131 MB)
__device__ __nv_bfloat16 d_hb[(size_t)BS * GS * E];     // bf16 copy of h (65 MB)
__device__ __nv_bfloat16 d_Wb[512 * 128];               // [n=j*128+f][k=e] bf16 (col-major B)
__device__ __nv_bfloat16 d_Wgb[4 * 384 * 128];          // r1_Wih|r1_Whh|r2_Wih|r2_Whh bf16
__device__ __nv_bfloat16 d_WQb[4 * 128 * 128];          // WQ1..WQ4 bf16
__device__ float d_logits[BS * GS];
__device__ float d_expsum[BS];
__device__ unsigned char d_mask[BS * GS];
__device__ int   d_vtt[BS * GS];
__device__ float d_q1[BS * E], d_q2[BS * E];
__device__ float d_iq1[BS * E], d_iq2[BS * E];
__device__ float d_Qp[BS * 512];                        // [Q1|Q2|Q3|Q4] per b
__device__ float d_hmean[BS * E];
__device__ int   d_ai[BS * 4];
__device__ int   d_kl[BS * 5];
__device__ int   d_kr[BS * 4];
__device__ int   d_nol[BS];
__device__ int   d_stopped[BS];
__device__ float d_ll[BS];

// ---------------- math helpers ----------------
__device__ __forceinline__ float fast_rcp(float x) {
    float r = __uint_as_float(0x7EF311C3u - __float_as_uint(x));
    r = r * (2.0f - x * r);
    r = r * (2.0f - x * r);
    return r;
}
__device__ __forceinline__ float tanh_fast(float x) {
    // Pade(5,4), clamp 3.6; abs err <= ~1e-3; fma/alu pipes only
    float xc = fminf(fmaxf(x, -3.6f), 3.6f);
    float x2 = xc * xc;
    float num = xc * fmaf(x2, x2 + 105.0f, 945.0f);
    float den = fmaf(x2, fmaf(15.0f, x2, 420.0f), 945.0f);
    return num * fast_rcp(den);
}
__device__ __forceinline__ float sigmoidf_(float x) { return 1.0f / (1.0f + expf(-x)); }

// pack two f32 -> e4m3x2 (byte0 = a, byte1 = b)
__device__ __forceinline__ unsigned short fp8pack(float a, float b) {
    unsigned short p;
    asm("cvt.rn.satfinite.e4m3x2.f32 %0, %1, %2;" : "=h"(p) : "f"(b), "f"(a));
    return p;
}
// 4 e4m3 bytes -> 4 floats (o[0] = byte0 ...)
__device__ __forceinline__ void fp8x4_to_f32(unsigned u, float* o) {
    unsigned h01, h23;
    asm("{\n\t.reg .b16 lo, hi;\n\t"
        "mov.b32 {lo, hi}, %2;\n\t"
        "cvt.rn.f16x2.e4m3x2 %0, lo;\n\t"
        "cvt.rn.f16x2.e4m3x2 %1, hi;\n\t}"
        : "=r"(h01), "=r"(h23) : "r"(u));
    float2 x = __half22float2(*reinterpret_cast<__half2*>(&h01));
    float2 y = __half22float2(*reinterpret_cast<__half2*>(&h23));
    o[0] = x.x; o[1] = x.y; o[2] = y.x; o[3] = y.y;
}
__device__ __forceinline__ float2 bf2f(unsigned u) {
    return __bfloat1622float2(*reinterpret_cast<__nv_bfloat162*>(&u));
}
__device__ __forceinline__ void cp_async16(void* smem_dst, const void* gsrc) {
    unsigned daddr = (unsigned)__cvta_generic_to_shared(smem_dst);
    asm volatile("cp.async.cg.shared.global [%0], [%1], 16;" :: "r"(daddr), "l"(gsrc) : "memory");
}

#define LDSM4(r, addr) \
    asm volatile("ldmatrix.sync.aligned.m8n8.x4.shared.b16 {%0,%1,%2,%3}, [%4];" \
                 : "=r"((r)[0]), "=r"((r)[1]), "=r"((r)[2]), "=r"((r)[3]) : "r"(addr))

#define MMA16816(c, a, b0, b1) \
    asm volatile("mma.sync.aligned.m16n8k16.row.col.f32.bf16.bf16.f32 " \
                 "{%0,%1,%2,%3},{%4,%5,%6,%7},{%8,%9},{%0,%1,%2,%3};" \
                 : "+f"((c)[0]), "+f"((c)[1]), "+f"((c)[2]), "+f"((c)[3]) \
                 : "r"((a)[0]), "r"((a)[1]), "r"((a)[2]), "r"((a)[3]), "r"(b0), "r"(b1))

// bf16 dot-8 helper: w4 = uint4 of 8 bf16; xp points at 8 smem floats (2x float4)
#define DOT8(acc, w4, xp)                                            \
    do {                                                             \
        float2 _p; float4 _x0 = (xp)[0], _x1 = (xp)[1];              \
        _p = bf2f((w4).x); acc = fmaf(_p.x, _x0.x, acc); acc = fmaf(_p.y, _x0.y, acc); \
        _p = bf2f((w4).y); acc = fmaf(_p.x, _x0.z, acc); acc = fmaf(_p.y, _x0.w, acc); \
        _p = bf2f((w4).z); acc = fmaf(_p.x, _x1.x, acc); acc = fmaf(_p.y, _x1.y, acc); \
        _p = bf2f((w4).w); acc = fmaf(_p.x, _x1.z, acc); acc = fmaf(_p.y, _x1.w, acc); \
    } while (0)

// ---------------- setup kernels ----------------
__global__ void convert_w(const float* __restrict__ W1, const float* __restrict__ W2,
                          const float* __restrict__ W3, const float* __restrict__ W4) {
    int idx = blockIdx.x * blockDim.x + threadIdx.x;    // 65536
    if (idx >= 512 * 128) return;
    int j = idx >> 14, r = idx & 16383;
    const float* W = (j == 0) ? W1 : (j == 1) ? W2 : (j == 2) ? W3 : W4;
    d_Wb[idx] = __float2bfloat16(W[r]);
}

__global__ void convert_wsmall(const float* __restrict__ g0, const float* __restrict__ g1,
                               const float* __restrict__ g2, const float* __restrict__ g3,
                               const float* __restrict__ q0, const float* __restrict__ q1,
                               const float* __restrict__ q2, const float* __restrict__ q3) {
    int idx = blockIdx.x * blockDim.x + threadIdx.x;    // 262144 total
    if (idx < 4 * 49152) {
        int m = idx / 49152, r = idx % 49152;
        const float* W = (m == 0) ? g0 : (m == 1) ? g1 : (m == 2) ? g2 : g3;
        d_Wgb[idx] = __float2bfloat16(W[r]);
    } else if (idx < 4 * 49152 + 4 * 16384) {
        int k = idx - 4 * 49152;
        int m = k / 16384, r = k % 16384;
        const float* W = (m == 0) ? q0 : (m == 1) ? q1 : (m == 2) ? q2 : q3;
        d_WQb[k] = __float2bfloat16(W[r]);
    }
}

// mean over g AND bf16 conversion of h (single streaming pass over h)
__global__ void hmean_kernel(const float* __restrict__ h) {
    int b = blockIdx.x, t = threadIdx.x;                 // 512 threads
    int e = t & 127, q = t >> 7;
    __shared__ float part[4][128];
    float s = 0.f;
    for (int g = q * 500; g < (q + 1) * 500; g++) {
        size_t idx = ((size_t)b * GS + g) * E + e;
        float v = h[idx];
        s += v;
        d_hb[idx] = __float2bfloat16(v);
    }
    part[q][e] = s;
    __syncthreads();
    if (t < 128)
        d_hmean[b * E + t] = (part[0][t] + part[1][t] + part[2][t] + part[3][t]) * (1.0f / GS);
}

__global__ void init_kernel(const float* __restrict__ W_init, const float* __restrict__ b_init,
                            const float* __restrict__ init_query) {
    int b = blockIdx.x, t = threadIdx.x;                 // 128 threads
    __shared__ __align__(16) float sm[E];
    sm[t] = d_hmean[b * E + t];
    __syncthreads();
    float acc = b_init[t];
    const float4* w = (const float4*)(W_init + t * E);
    const float4* x = (const float4*)sm;
#pragma unroll 8
    for (int e4 = 0; e4 < E / 4; e4++) {
        float4 a = w[e4], v = x[e4];
        acc = fmaf(a.x, v.x, acc); acc = fmaf(a.y, v.y, acc);
        acc = fmaf(a.z, v.z, acc); acc = fmaf(a.w, v.w, acc);
    }
    d_q1[b * E + t] = acc;
    d_q2[b * E + t] = acc;
    float iq = init_query[t];
    d_iq1[b * E + t] = iq;
    d_iq2[b * E + t] = iq;
    if (t == 0) { d_stopped[b] = 1; d_nol[b] = -1; d_ll[b] = 0.0f; }
    if (t < 5) d_kl[b * 5 + t] = 0;
    if (t < 4) { d_ai[b * 4 + t] = 0; d_kr[b * 4 + t] = 0; }
}

// ---------------- bf16 MMA GEMM: Kc8 = e4m3(hb @ W^T) ----------------
// Tile 128m x 64n, 256 threads (8 warps = 4m x 2n), warp does 32x32.
// Full K=128 resident; A+B staged via cp.async, ONE barrier, 8 k-steps.
// Dynamic smem 52224B (needs cudaFuncSetAttribute).
// grid (8_n, 2000_m): n fastest -> A tile L2-resident across its 8 n-blocks.
#define GEMM_SMEM ((128 * 136 + 64 * 136) * 2)
__global__ void __launch_bounds__(256) gemm_kernel() {
    extern __shared__ __align__(16) char smem_raw[];
    __nv_bfloat16 (*As)[136] = (__nv_bfloat16(*)[136])smem_raw;
    __nv_bfloat16 (*Bs)[136] = (__nv_bfloat16(*)[136])(smem_raw + 128 * 136 * 2);
    const int t = threadIdx.x;
    const int warp = t >> 5, lane = t & 31;
    const int n0 = blockIdx.x * 64, m0 = blockIdx.y * 128;
    const int wm = (warp >> 1) * 32, wn = (warp & 1) * 32;

    // stage A (128 rows x 128 k bf16) and B (64 x 128) via cp.async
#pragma unroll
    for (int i = t; i < 128 * 16; i += 256) {
        int row = i >> 4, c8 = i & 15;
        cp_async16(&As[row][c8 * 8], d_hb + (size_t)(m0 + row) * 128 + c8 * 8);
    }
#pragma unroll
    for (int i = t; i < 64 * 16; i += 256) {
        int n = i >> 4, c8 = i & 15;
        cp_async16(&Bs[n][c8 * 8], d_Wb + (size_t)(n0 + n) * 128 + c8 * 8);
    }
    asm volatile("cp.async.commit_group;\ncp.async.wait_group 0;" ::: "memory");
    __syncthreads();

    float c[2][4][4];
#pragma unroll
    for (int i = 0; i < 2; i++)
#pragma unroll
        for (int j = 0; j < 4; j++)
#pragma unroll
            for (int k = 0; k < 4; k++) c[i][j][k] = 0.f;

    // ldmatrix lane address mapping (272B row stride: conflict-free, offsets mod 128 distinct)
    const int a_row = (lane & 15), a_colh = (lane >> 4) * 8;
    const int b_row = ((lane >> 4) & 1) * 8 + (lane & 7);
    const int b_colh = ((lane >> 3) & 1) * 8;

    unsigned a_addr0 = (unsigned)__cvta_generic_to_shared(&As[wm + a_row][a_colh]);
    unsigned a_addr1 = (unsigned)__cvta_generic_to_shared(&As[wm + 16 + a_row][a_colh]);
    unsigned b_addr0 = (unsigned)__cvta_generic_to_shared(&Bs[wn + b_row][b_colh]);
    unsigned b_addr1 = (unsigned)__cvta_generic_to_shared(&Bs[wn + 16 + b_row][b_colh]);

#pragma unroll
    for (int ks = 0; ks < 8; ks++) {
        unsigned koff = ks * 32;                 // 16 bf16 cols
        unsigned af0[4], af1[4], bf0[4], bf1[4];
        LDSM4(af0, a_addr0 + koff);
        LDSM4(af1, a_addr1 + koff);
        LDSM4(bf0, b_addr0 + koff);
        LDSM4(bf1, b_addr1 + koff);
        MMA16816(c[0][0], af0, bf0[0], bf0[1]);
        MMA16816(c[0][1], af0, bf0[2], bf0[3]);
        MMA16816(c[0][2], af0, bf1[0], bf1[1]);
        MMA16816(c[0][3], af0, bf1[2], bf1[3]);
        MMA16816(c[1][0], af1, bf0[0], bf0[1]);
        MMA16816(c[1][1], af1, bf0[2], bf0[3]);
        MMA16816(c[1][2], af1, bf1[0], bf1[1]);
        MMA16816(c[1][3], af1, bf1[2], bf1[3]);
    }

    // epilogue: e4m3 store (2 bytes per fragment row-pair)
    const int qr = lane >> 2, qc = lane & 3;
#pragma unroll
    for (int mf = 0; mf < 2; mf++)
#pragma unroll
        for (int nf = 0; nf < 4; nf++) {
            int row = m0 + wm + mf * 16 + qr;
            int col = n0 + wn + nf * 8 + qc * 2;
            unsigned short p0 = fp8pack(c[mf][nf][0], c[mf][nf][1]);
            unsigned short p1 = fp8pack(c[mf][nf][2], c[mf][nf][3]);
            *(unsigned short*)(d_Kc8 + (size_t)row * 512 + col) = p0;
            *(unsigned short*)(d_Kc8 + (size_t)(row + 8) * 512 + col) = p1;
        }
}

// ---------------- per-iteration kernels ----------------
__global__ void gru_kernel(const float* __restrict__ bih1, const float* __restrict__ bhh1,
                           const float* __restrict__ bih2, const float* __restrict__ bhh2) {
    int b = blockIdx.x, r = blockIdx.y, t = threadIdx.x;   // 384 threads
    const float* bih = r ? bih2 : bih1;
    const float* bhh = r ? bhh2 : bhh1;
    float* q = r ? d_q2 : d_q1;
    const float* iq = r ? d_iq2 : d_iq1;

    __shared__ __align__(16) float sx[E], sh[E];
    __shared__ float gi[3 * E], gh[3 * E];
    if (t < E) { sx[t] = iq[b * E + t]; sh[t] = q[b * E + t]; }
    __syncthreads();

    float a = bih[t], cgh = bhh[t];
    const uint4* wi = (const uint4*)(d_Wgb + ((size_t)(r * 2) * 384 + t) * 128);
    const uint4* wh = (const uint4*)(d_Wgb + ((size_t)(r * 2 + 1) * 384 + t) * 128);
    const float4* x4 = (const float4*)sx;
    const float4* h4 = (const float4*)sh;
#pragma unroll 4
    for (int e8 = 0; e8 < E / 8; e8++) {
        uint4 wa = wi[e8], wb = wh[e8];
        DOT8(a, wa, x4 + e8 * 2);
        DOT8(cgh, wb, h4 + e8 * 2);
    }
    gi[t] = a; gh[t] = cgh;
    __syncthreads();
    if (t < E) {
        float rr = sigmoidf_(gi[t] + gh[t]);
        float z  = sigmoidf_(gi[E + t] + gh[E + t]);
        float n  = tanhf(gi[2 * E + t] + rr * gh[2 * E + t]);
        q[b * E + t] = (1.0f - z) * n + z * sh[t];
    }
}

__global__ void qproj_kernel() {
    int b = blockIdx.x, t = threadIdx.x;                    // 512 threads
    __shared__ __align__(16) float s1[E], s2[E];
    if (t < E) s1[t] = d_q1[b * E + t];
    else if (t < 2 * E) s2[t - E] = d_q2[b * E + t - E];
    if (t == 0) d_expsum[b] = 0.0f;    // reset for this iteration's score pass
    __syncthreads();
    int j = t >> 7, f = t & 127;
    const uint4* w = (const uint4*)(d_WQb + ((size_t)j * 128 + f) * 128);
    const float4* x = (const float4*)((j == 0 || j == 2) ? s1 : s2);
    float acc = 0.f;
#pragma unroll 4
    for (int e8 = 0; e8 < E / 8; e8++) {
        uint4 wa = w[e8];
        DOT8(acc, wa, x + e8 * 2);
    }
    d_Qp[b * 512 + t] = acc;
}

// 2 g-rows per warp: grid (BS, 125), 256 threads -> 16 rows per block
__global__ void __launch_bounds__(256) score_kernel(int iter, const int* __restrict__ last_action,
                                                    const float* __restrict__ V1,
                                                    const float* __restrict__ V2) {
    int b = blockIdx.x, t = threadIdx.x;
    int warp = t >> 5, lane = t & 31;
    __shared__ float sQ[512];
    __shared__ float sV[256];
    __shared__ float sE[8];
    sQ[t] = d_Qp[b * 512 + t];
    sQ[256 + t] = d_Qp[b * 512 + 256 + t];
    sV[t] = (t < 128) ? V1[t] : V2[t - 128];
    __syncthreads();

    int g0 = blockIdx.y * 16 + warp * 2;
    const unsigned char* __restrict__ Kc = d_Kc8 + ((size_t)b * GS + g0) * 512;
    int f0 = lane * 4;
    // issue all 8 row loads up front (MLP)
    unsigned a1 = *(const unsigned*)(Kc + f0);
    unsigned a2 = *(const unsigned*)(Kc + 128 + f0);
    unsigned a3 = *(const unsigned*)(Kc + 256 + f0);
    unsigned a4 = *(const unsigned*)(Kc + 384 + f0);
    unsigned b1 = *(const unsigned*)(Kc + 512 + f0);
    unsigned b2 = *(const unsigned*)(Kc + 640 + f0);
    unsigned b3 = *(const unsigned*)(Kc + 768 + f0);
    unsigned b4 = *(const unsigned*)(Kc + 896 + f0);

    float k1[4], k2[4], k3[4], k4[4];
    float s0 = 0.f, s1 = 0.f;
    fp8x4_to_f32(a1, k1); fp8x4_to_f32(a2, k2);
    fp8x4_to_f32(a3, k3); fp8x4_to_f32(a4, k4);
#pragma unroll
    for (int i = 0; i < 4; i++) {
        int f = f0 + i;
        float v1 = fmaf(k3[i], sQ[256 + f], k1[i] + sQ[f]);
        float v2 = fmaf(k4[i], sQ[384 + f], k2[i] + sQ[128 + f]);
        s0 = fmaf(sV[f], tanh_fast(v1), s0);
        s0 = fmaf(sV[128 + f], tanh_fast(v2), s0);
    }
    fp8x4_to_f32(b1, k1); fp8x4_to_f32(b2, k2);
    fp8x4_to_f32(b3, k3); fp8x4_to_f32(b4, k4);
#pragma unroll
    for (int i = 0; i < 4; i++) {
        int f = f0 + i;
        float v1 = fmaf(k3[i], sQ[256 + f], k1[i] + sQ[f]);
        float v2 = fmaf(k4[i], sQ[384 + f], k2[i] + sQ[128 + f]);
        s1 = fmaf(sV[f], tanh_fast(v1), s1);
        s1 = fmaf(sV[128 + f], tanh_fast(v2), s1);
    }
#pragma unroll
    for (int o = 16; o; o >>= 1) {
        s0 += __shfl_xor_sync(0xFFFFFFFFu, s0, o);
        s1 += __shfl_xor_sync(0xFFFFFFFFu, s1, o);
    }
    if (lane == 0) {
        float lg0 = tanhf(s0) * CLIPV;
        float lg1 = tanhf(s1) * CLIPV;
        bool m0, m1;
        if (iter == 0) {
            int la = last_action[b];
            m0 = (g0 == la); m1 = (g0 + 1 == la);
        } else {
            m0 = d_mask[b * GS + g0] != 0;
            m1 = d_mask[b * GS + g0 + 1] != 0;
        }
        d_logits[b * GS + g0] = m0 ? NEGV : lg0;
        d_logits[b * GS + g0 + 1] = m1 ? NEGV : lg1;
        float e0 = m0 ? 0.0f : expf(lg0 - CLIPV);
        float e1 = m1 ? 0.0f : expf(lg1 - CLIPV);
        sE[warp] = e0 + e1;
    }
    __syncthreads();
    if (t == 0) {
        float e = sE[0];
#pragma unroll
        for (int i = 1; i < 8; i++) e += sE[i];
        atomicAdd(&d_expsum[b], e);
    }
}

__global__ void __launch_bounds__(256) update_kernel(int iter, const int* __restrict__ rec,
                                                     const int* __restrict__ vt,
                                                     const float* __restrict__ h,
                                                     const int* __restrict__ fixed_action) {
    int b = blockIdx.x, t = threadIdx.x;   // 256 threads, one block per b
    __shared__ int s_action, s_stopold, s_stopnew, s_nolmod, s_allow, s_ai0;

    const int bG = b * GS;

    if (t == 0) {
        int stop_old = d_stopped[b];
        int nol_old  = d_nol[b];
        int ai0_old  = d_ai[b * 4];
        int action   = (iter > 0 && stop_old) ? ai0_old : fixed_action[b * KM + iter];

        // expsum == 0 exactly <=> ALL logits masked. Reference's shifted
        // log-softmax gives logp[action] = -log(GS) in that case.
        float es = d_expsum[b];
        float loss = (es > 0.0f) ? (d_logits[bG + action] - (CLIPV + logf(es)))
                                 : (-logf((float)GS));
        if (iter == 0) d_ll[b] += loss;
        else if (!stop_old) d_ll[b] += loss;

        int nna = rec[bG + action];
        d_ai[b * 4 + iter] = action;
        if (stop_old) d_kl[b * 5 + iter] = action;
        int krm1 = ((iter - 1) + KM) % KM;
        if (!stop_old) d_kr[b * 4 + krm1] = action;
        d_kl[b * 5 + iter + 1] = nna;

        int eq = (action == nol_old) ? 1 : 0;
        int stop_new = (iter == 0) ? eq : (stop_old | eq);
        if (stop_new) {
            int klm1 = ((iter - 1) + 5) % 5;
            d_kl[b * 5 + iter] = d_kl[b * 5 + klm1];
            d_kr[b * 4 + iter] = d_kr[b * 4 + krm1];
        }
        d_stopped[b] = stop_new;
        d_nol[b] = stop_new ? -1 : nna;

        int ai0 = (iter == 0) ? action : ai0_old;
        s_action = action;
        s_stopold = stop_old;
        s_stopnew = stop_new;
        s_nolmod = ((nol_old % GS) + GS) % GS;   // Python floored mod
        s_ai0 = ai0;
        s_allow = (!stop_new && nna == ai0) ? 1 : 0;
    }
    __syncthreads();

    int act = s_action;
    int va = (iter == 0) ? 0 : d_vtt[bG + act];
    int vta = (iter == 0) ? vt[bG + act] : 0;
    for (int g = t; g < GS; g += 256) {
        int v;
        if (iter == 0) {
            v = (((vt[bG + g] - vta) % GS) + GS) % GS;
            d_vtt[bG + g] = v;
        } else {
            v = d_vtt[bG + g];
        }
        bool m = (v <= va);
        if (iter == 0) m = m || (v > GS - 2);
        if (s_stopnew && g == act) m = false;
        if (s_allow && g == s_ai0) m = false;
        d_mask[bG + g] = m ? 1 : 0;
    }

    if (t < E) {
        float hq1 = h[((size_t)bG + act) * E + t];
        d_iq1[b * E + t] = hq1;
        d_iq2[b * E + t] = s_stopold ? hq1 : h[((size_t)bG + s_nolmod) * E + t];
    }
}

// ---------------- output ----------------
__global__ void out_kernel(float* __restrict__ out) {
    int idx = blockIdx.x * 256 + threadIdx.x;
    if (idx < BS * 12) {
        int b = idx / 12, j = idx % 12;
        int v;
        if (j < 4) v = d_ai[b * 4 + j];
        else if (j < 8) v = d_kl[b * 5 + (j - 4)];
        else {
            int jj = j - 8;
            if (jj == 3 && !d_stopped[b]) v = d_kl[b * 5 + 4];  // post-loop kr fix
            else v = d_kr[b * 4 + jj];
        }
        out[idx] = (float)v;
    } else if (idx < BS * 12 + BS) {
        out[idx] = d_ll[idx - BS * 12];
    }
}

// ---------------- launch ----------------
extern "C" void kernel_launch(void* const* d_in, const int* in_sizes, int n_in,
                              void* d_out, int out_size) {
    (void)in_sizes; (void)n_in; (void)out_size;
    const float* h            = (const float*)d_in[0];
    const int*   rec          = (const int*)  d_in[1];
    /* context2 d_in[2] unused */
    const int*   visited_time = (const int*)  d_in[3];
    const int*   last_action  = (const int*)  d_in[4];
    const int*   fixed_action = (const int*)  d_in[5];
    const float* W_K1 = (const float*)d_in[6];
    const float* W_K2 = (const float*)d_in[7];
    const float* W_K3 = (const float*)d_in[8];
    const float* W_K4 = (const float*)d_in[9];
    const float* W_Q1 = (const float*)d_in[10];
    const float* W_Q2 = (const float*)d_in[11];
    const float* W_Q3 = (const float*)d_in[12];
    const float* W_Q4 = (const float*)d_in[13];
    const float* W_init     = (const float*)d_in[14];
    const float* b_init     = (const float*)d_in[15];
    const float* V1         = (const float*)d_in[16];
    const float* V2         = (const float*)d_in[17];
    const float* init_query = (const float*)d_in[18];
    const float* r1_Wih = (const float*)d_in[19];
    const float* r1_Whh = (const float*)d_in[20];
    const float* r1_bih = (const float*)d_in[21];
    const float* r1_bhh = (const float*)d_in[22];
    const float* r2_Wih = (const float*)d_in[23];
    const float* r2_Whh = (const float*)d_in[24];
    const float* r2_bih = (const float*)d_in[25];
    const float* r2_bhh = (const float*)d_in[26];

    static int smem_set = 0;
    if (!smem_set) {
        cudaFuncSetAttribute(gemm_kernel, cudaFuncAttributeMaxDynamicSharedMemorySize,
                             GEMM_SMEM);
        smem_set = 1;
    }

    convert_w<<<256, 256>>>(W_K1, W_K2, W_K3, W_K4);
    convert_wsmall<<<1024, 256>>>(r1_Wih, r1_Whh, r2_Wih, r2_Whh,
                                  W_Q1, W_Q2, W_Q3, W_Q4);
    hmean_kernel<<<BS, 512>>>(h);
    init_kernel<<<BS, 128>>>(W_init, b_init, init_query);
    gemm_kernel<<<dim3(8, 2000), 256, GEMM_SMEM>>>();   // n fastest -> A tile L2 reuse

    for (int i = 0; i < KM; i++) {
        gru_kernel<<<dim3(BS, 2), 384>>>(r1_bih, r1_bhh, r2_bih, r2_bhh);
        qproj_kernel<<<BS, 512>>>();
        score_kernel<<<dim3(BS, 125), 256>>>(i, last_action, V1, V2);
        update_kernel<<<BS, 256>>>(i, rec, visited_time, h, fixed_action);
    }
    out_kernel<<<7, 256>>>((float*)d_out);
}

// round 14
// speedup vs baseline: 2.0892x; 1.0633x over previous
#include <cuda_runtime.h>
#include <cuda_bf16.h>
#include <cuda_fp16.h>
#include <math.h>
#include <stdint.h>

#define BS   128
#define GS   2000
#define E    128
#define KM   4
#define NEGV (-1.0e30f)
#define CLIPV 10.0f

// ---------------- device scratch (static globals; no runtime allocation) ----------------
__device__ unsigned char d_Kc8[(size_t)BS * GS * 512];  // [b][g][K1|K2|K3|K4] e4m3 (131 MB)
__device__ __nv_bfloat16 d_hb[(size_t)BS * GS * E];     // bf16 copy of h (65 MB)
__device__ __nv_bfloat16 d_Wb[512 * 128];               // [n=j*128+f][k=e] bf16 (col-major B)
__device__ __nv_bfloat16 d_Wgb[4 * 384 * 128];          // r1_Wih|r1_Whh|r2_Wih|r2_Whh bf16
__device__ __nv_bfloat16 d_WQb[4 * 128 * 128];          // WQ1..WQ4 bf16
__device__ int   d_vtt[BS * GS];
__device__ float d_q1[BS * E], d_q2[BS * E];
__device__ float d_Qp[(size_t)KM * BS * 512];           // [iter][b][Q1|Q2|Q3|Q4]
__device__ float d_hmean[BS * E];
__device__ int   d_ai[BS * 4];
__device__ int   d_kl[BS * 5];
__device__ int   d_kr[BS * 4];
__device__ int   d_stopped[BS];
__device__ float d_ll[BS];
// precomputed per-iteration scalars (written by precompute_kernel)
__device__ int   d_gact[KM * BS];      // action_i
__device__ int   d_gstopold[KM * BS];  // stopped entering iter i
__device__ int   d_gnolmod[KM * BS];   // (nol entering iter i) floored-mod GS
__device__ int   d_mva[KM * BS];       // mask params for score-iter si (si>=1)
__device__ int   d_mstopnew[KM * BS];
__device__ int   d_mact[KM * BS];
__device__ int   d_mallow[KM * BS];
__device__ int   d_mai0[KM * BS];
__device__ float d_expsum4[KM * BS];
__device__ float d_logact4[KM * BS];

// ---------------- math helpers ----------------
__device__ __forceinline__ float fast_rcp(float x) {
    float r = __uint_as_float(0x7EF311C3u - __float_as_uint(x));
    r = r * (2.0f - x * r);
    r = r * (2.0f - x * r);
    return r;
}
__device__ __forceinline__ float tanh_fast(float x) {
    // Pade(5,4), clamp 3.6; abs err <= ~1e-3; fma/alu pipes only
    float xc = fminf(fmaxf(x, -3.6f), 3.6f);
    float x2 = xc * xc;
    float num = xc * fmaf(x2, x2 + 105.0f, 945.0f);
    float den = fmaf(x2, fmaf(15.0f, x2, 420.0f), 945.0f);
    return num * fast_rcp(den);
}
__device__ __forceinline__ float sigmoidf_(float x) { return 1.0f / (1.0f + expf(-x)); }

__device__ __forceinline__ unsigned short fp8pack(float a, float b) {
    unsigned short p;
    asm("cvt.rn.satfinite.e4m3x2.f32 %0, %1, %2;" : "=h"(p) : "f"(b), "f"(a));
    return p;
}
__device__ __forceinline__ void fp8x4_to_f32(unsigned u, float* o) {
    unsigned h01, h23;
    asm("{\n\t.reg .b16 lo, hi;\n\t"
        "mov.b32 {lo, hi}, %2;\n\t"
        "cvt.rn.f16x2.e4m3x2 %0, lo;\n\t"
        "cvt.rn.f16x2.e4m3x2 %1, hi;\n\t}"
        : "=r"(h01), "=r"(h23) : "r"(u));
    float2 x = __half22float2(*reinterpret_cast<__half2*>(&h01));
    float2 y = __half22float2(*reinterpret_cast<__half2*>(&h23));
    o[0] = x.x; o[1] = x.y; o[2] = y.x; o[3] = y.y;
}
__device__ __forceinline__ float2 bf2f(unsigned u) {
    return __bfloat1622float2(*reinterpret_cast<__nv_bfloat162*>(&u));
}
__device__ __forceinline__ void cp_async16(void* smem_dst, const void* gsrc) {
    unsigned daddr = (unsigned)__cvta_generic_to_shared(smem_dst);
    asm volatile("cp.async.cg.shared.global [%0], [%1], 16;" :: "r"(daddr), "l"(gsrc) : "memory");
}

#define LDSM4(r, addr) \
    asm volatile("ldmatrix.sync.aligned.m8n8.x4.shared.b16 {%0,%1,%2,%3}, [%4];" \
                 : "=r"((r)[0]), "=r"((r)[1]), "=r"((r)[2]), "=r"((r)[3]) : "r"(addr))

#define MMA16816(c, a, b0, b1) \
    asm volatile("mma.sync.aligned.m16n8k16.row.col.f32.bf16.bf16.f32 " \
                 "{%0,%1,%2,%3},{%4,%5,%6,%7},{%8,%9},{%0,%1,%2,%3};" \
                 : "+f"((c)[0]), "+f"((c)[1]), "+f"((c)[2]), "+f"((c)[3]) \
                 : "r"((a)[0]), "r"((a)[1]), "r"((a)[2]), "r"((a)[3]), "r"(b0), "r"(b1))

#define DOT8(acc, w4, xp)                                            \
    do {                                                             \
        float2 _p; float4 _x0 = (xp)[0], _x1 = (xp)[1];              \
        _p = bf2f((w4).x); acc = fmaf(_p.x, _x0.x, acc); acc = fmaf(_p.y, _x0.y, acc); \
        _p = bf2f((w4).y); acc = fmaf(_p.x, _x0.z, acc); acc = fmaf(_p.y, _x0.w, acc); \
        _p = bf2f((w4).z); acc = fmaf(_p.x, _x1.x, acc); acc = fmaf(_p.y, _x1.y, acc); \
        _p = bf2f((w4).w); acc = fmaf(_p.x, _x1.z, acc); acc = fmaf(_p.y, _x1.w, acc); \
    } while (0)

// ---------------- setup kernels ----------------
__global__ void convert_w(const float* __restrict__ W1, const float* __restrict__ W2,
                          const float* __restrict__ W3, const float* __restrict__ W4) {
    int idx = blockIdx.x * blockDim.x + threadIdx.x;    // 65536
    if (idx >= 512 * 128) return;
    int j = idx >> 14, r = idx & 16383;
    const float* W = (j == 0) ? W1 : (j == 1) ? W2 : (j == 2) ? W3 : W4;
    d_Wb[idx] = __float2bfloat16(W[r]);
}

__global__ void convert_wsmall(const float* __restrict__ g0, const float* __restrict__ g1,
                               const float* __restrict__ g2, const float* __restrict__ g3,
                               const float* __restrict__ q0, const float* __restrict__ q1,
                               const float* __restrict__ q2, const float* __restrict__ q3) {
    int idx = blockIdx.x * blockDim.x + threadIdx.x;
    if (idx < 4 * 49152) {
        int m = idx / 49152, r = idx % 49152;
        const float* W = (m == 0) ? g0 : (m == 1) ? g1 : (m == 2) ? g2 : g3;
        d_Wgb[idx] = __float2bfloat16(W[r]);
    } else if (idx < 4 * 49152 + 4 * 16384) {
        int k = idx - 4 * 49152;
        int m = k / 16384, r = k % 16384;
        const float* W = (m == 0) ? q0 : (m == 1) ? q1 : (m == 2) ? q2 : q3;
        d_WQb[k] = __float2bfloat16(W[r]);
    }
}

// mean over g AND bf16 conversion of h (single streaming pass over h)
__global__ void hmean_kernel(const float* __restrict__ h) {
    int b = blockIdx.x, t = threadIdx.x;                 // 512 threads
    int e = t & 127, q = t >> 7;
    __shared__ float part[4][128];
    float s = 0.f;
    for (int g = q * 500; g < (q + 1) * 500; g++) {
        size_t idx = ((size_t)b * GS + g) * E + e;
        float v = h[idx];
        s += v;
        d_hb[idx] = __float2bfloat16(v);
    }
    part[q][e] = s;
    __syncthreads();
    if (t < 128)
        d_hmean[b * E + t] = (part[0][t] + part[1][t] + part[2][t] + part[3][t]) * (1.0f / GS);
}

__global__ void vtt_kernel(const int* __restrict__ vt, const int* __restrict__ fixed_action) {
    int b = blockIdx.x, t = threadIdx.x;                 // 256 threads
    int bG = b * GS;
    int vta = vt[bG + fixed_action[b * KM]];             // iter-0 action is always fixed
    for (int g = t; g < GS; g += 256) {
        int d = vt[bG + g] - vta;                        // in (-GS, GS)
        d_vtt[bG + g] = (d + GS) % GS;                   // Python floored mod
    }
}

__global__ void init_kernel(const float* __restrict__ W_init, const float* __restrict__ b_init) {
    int b = blockIdx.x, t = threadIdx.x;                 // 128 threads
    __shared__ __align__(16) float sm[E];
    sm[t] = d_hmean[b * E + t];
    __syncthreads();
    float acc = b_init[t];
    const float4* w = (const float4*)(W_init + t * E);
    const float4* x = (const float4*)sm;
#pragma unroll 8
    for (int e4 = 0; e4 < E / 4; e4++) {
        float4 a = w[e4], v = x[e4];
        acc = fmaf(a.x, v.x, acc); acc = fmaf(a.y, v.y, acc);
        acc = fmaf(a.z, v.z, acc); acc = fmaf(a.w, v.w, acc);
    }
    d_q1[b * E + t] = acc;
    d_q2[b * E + t] = acc;
}

// ---- full 4-iteration integer bookkeeping simulation (one thread per b) ----
__global__ void precompute_kernel(const int* __restrict__ rec,
                                  const int* __restrict__ fixed_action) {
    int b = threadIdx.x;          // <<<1,128>>>
    if (b >= BS) return;
    const int bG = b * GS;
    int stopped = 1, nol = -1;
    int ai[4] = {0, 0, 0, 0};
    int kl[5] = {0, 0, 0, 0, 0};
    int kr[4] = {0, 0, 0, 0};
#pragma unroll
    for (int i = 0; i < KM; i++) {
        int stop_old = stopped;
        int action = (i > 0 && stop_old) ? ai[0] : fixed_action[b * KM + i];

        // GRU inputs for iter i+1
        d_gact[i * BS + b] = action;
        d_gstopold[i * BS + b] = stop_old;
        d_gnolmod[i * BS + b] = ((nol % GS) + GS) % GS;

        int nna = rec[bG + action];
        ai[i] = action;
        if (stop_old) kl[i] = action;
        int krm1 = ((i - 1) + KM) % KM;
        if (!stop_old) kr[krm1] = action;
        kl[i + 1] = nna;

        int eq = (action == nol) ? 1 : 0;
        int stop_new = (i == 0) ? eq : (stop_old | eq);
        if (stop_new) {
            kl[i] = kl[((i - 1) + 5) % 5];
            kr[i] = kr[krm1];
        }
        stopped = stop_new;
        nol = stop_new ? -1 : nna;
        int ai0 = ai[0];

        if (i + 1 < KM) {
            d_mva[(i + 1) * BS + b] = d_vtt[bG + action];
            d_mstopnew[(i + 1) * BS + b] = stop_new;
            d_mact[(i + 1) * BS + b] = action;
            d_mallow[(i + 1) * BS + b] = (!stop_new && nna == ai0) ? 1 : 0;
            d_mai0[(i + 1) * BS + b] = ai0;
        }
        d_expsum4[i * BS + b] = 0.0f;
    }
#pragma unroll
    for (int i = 0; i < 4; i++) d_ai[b * 4 + i] = ai[i];
#pragma unroll
    for (int i = 0; i < 5; i++) d_kl[b * 5 + i] = kl[i];
#pragma unroll
    for (int i = 0; i < 4; i++) d_kr[b * 4 + i] = kr[i];
    d_stopped[b] = stopped;
}

// ---------------- bf16 MMA GEMM: Kc8 = e4m3(hb @ W^T) ---------------- (r13, unchanged)
#define GEMM_SMEM ((128 * 136 + 64 * 136) * 2)
__global__ void __launch_bounds__(256) gemm_kernel() {
    extern __shared__ __align__(16) char smem_raw[];
    __nv_bfloat16 (*As)[136] = (__nv_bfloat16(*)[136])smem_raw;
    __nv_bfloat16 (*Bs)[136] = (__nv_bfloat16(*)[136])(smem_raw + 128 * 136 * 2);
    const int t = threadIdx.x;
    const int warp = t >> 5, lane = t & 31;
    const int n0 = blockIdx.x * 64, m0 = blockIdx.y * 128;
    const int wm = (warp >> 1) * 32, wn = (warp & 1) * 32;

#pragma unroll
    for (int i = t; i < 128 * 16; i += 256) {
        int row = i >> 4, c8 = i & 15;
        cp_async16(&As[row][c8 * 8], d_hb + (size_t)(m0 + row) * 128 + c8 * 8);
    }
#pragma unroll
    for (int i = t; i < 64 * 16; i += 256) {
        int n = i >> 4, c8 = i & 15;
        cp_async16(&Bs[n][c8 * 8], d_Wb + (size_t)(n0 + n) * 128 + c8 * 8);
    }
    asm volatile("cp.async.commit_group;\ncp.async.wait_group 0;" ::: "memory");
    __syncthreads();

    float c[2][4][4];
#pragma unroll
    for (int i = 0; i < 2; i++)
#pragma unroll
        for (int j = 0; j < 4; j++)
#pragma unroll
            for (int k = 0; k < 4; k++) c[i][j][k] = 0.f;

    const int a_row = (lane & 15), a_colh = (lane >> 4) * 8;
    const int b_row = ((lane >> 4) & 1) * 8 + (lane & 7);
    const int b_colh = ((lane >> 3) & 1) * 8;

    unsigned a_addr0 = (unsigned)__cvta_generic_to_shared(&As[wm + a_row][a_colh]);
    unsigned a_addr1 = (unsigned)__cvta_generic_to_shared(&As[wm + 16 + a_row][a_colh]);
    unsigned b_addr0 = (unsigned)__cvta_generic_to_shared(&Bs[wn + b_row][b_colh]);
    unsigned b_addr1 = (unsigned)__cvta_generic_to_shared(&Bs[wn + 16 + b_row][b_colh]);

#pragma unroll
    for (int ks = 0; ks < 8; ks++) {
        unsigned koff = ks * 32;
        unsigned af0[4], af1[4], bf0[4], bf1[4];
        LDSM4(af0, a_addr0 + koff);
        LDSM4(af1, a_addr1 + koff);
        LDSM4(bf0, b_addr0 + koff);
        LDSM4(bf1, b_addr1 + koff);
        MMA16816(c[0][0], af0, bf0[0], bf0[1]);
        MMA16816(c[0][1], af0, bf0[2], bf0[3]);
        MMA16816(c[0][2], af0, bf1[0], bf1[1]);
        MMA16816(c[0][3], af0, bf1[2], bf1[3]);
        MMA16816(c[1][0], af1, bf0[0], bf0[1]);
        MMA16816(c[1][1], af1, bf0[2], bf0[3]);
        MMA16816(c[1][2], af1, bf1[0], bf1[1]);
        MMA16816(c[1][3], af1, bf1[2], bf1[3]);
    }

    const int qr = lane >> 2, qc = lane & 3;
#pragma unroll
    for (int mf = 0; mf < 2; mf++)
#pragma unroll
        for (int nf = 0; nf < 4; nf++) {
            int row = m0 + wm + mf * 16 + qr;
            int col = n0 + wn + nf * 8 + qc * 2;
            unsigned short p0 = fp8pack(c[mf][nf][0], c[mf][nf][1]);
            unsigned short p1 = fp8pack(c[mf][nf][2], c[mf][nf][3]);
            *(unsigned short*)(d_Kc8 + (size_t)row * 512 + col) = p0;
            *(unsigned short*)(d_Kc8 + (size_t)(row + 8) * 512 + col) = p1;
        }
}

// ---------------- GRU (r13 shape; input gather from precomputed scalars) ----------------
__global__ void gru_kernel(int iter, const float* __restrict__ h,
                           const float* __restrict__ init_query,
                           const float* __restrict__ bih1, const float* __restrict__ bhh1,
                           const float* __restrict__ bih2, const float* __restrict__ bhh2) {
    int b = blockIdx.x, r = blockIdx.y, t = threadIdx.x;   // 384 threads
    const float* bih = r ? bih2 : bih1;
    const float* bhh = r ? bhh2 : bhh1;
    float* q = r ? d_q2 : d_q1;

    __shared__ __align__(16) float sx[E], sh[E];
    __shared__ float gi[3 * E], gh[3 * E];
    if (t < E) {
        float x;
        if (iter == 0) {
            x = init_query[t];
        } else {
            int idx = (iter - 1) * BS + b;
            int act = d_gact[idx];
            if (r == 0) {
                x = h[((size_t)b * GS + act) * E + t];
            } else {
                int gg = d_gstopold[idx] ? act : d_gnolmod[idx];
                x = h[((size_t)b * GS + gg) * E + t];
            }
        }
        sx[t] = x; sh[t] = q[b * E + t];
    }
    __syncthreads();

    float a = bih[t], cgh = bhh[t];
    const uint4* wi = (const uint4*)(d_Wgb + ((size_t)(r * 2) * 384 + t) * 128);
    const uint4* wh = (const uint4*)(d_Wgb + ((size_t)(r * 2 + 1) * 384 + t) * 128);
    const float4* x4 = (const float4*)sx;
    const float4* h4 = (const float4*)sh;
#pragma unroll 4
    for (int e8 = 0; e8 < E / 8; e8++) {
        uint4 wa = wi[e8], wb = wh[e8];
        DOT8(a, wa, x4 + e8 * 2);
        DOT8(cgh, wb, h4 + e8 * 2);
    }
    gi[t] = a; gh[t] = cgh;
    __syncthreads();
    if (t < E) {
        float rr = sigmoidf_(gi[t] + gh[t]);
        float z  = sigmoidf_(gi[E + t] + gh[E + t]);
        float n  = tanhf(gi[2 * E + t] + rr * gh[2 * E + t]);
        q[b * E + t] = (1.0f - z) * n + z * sh[t];
    }
}

__global__ void qproj_kernel(int iter) {
    int b = blockIdx.x, t = threadIdx.x;                    // 512 threads
    __shared__ __align__(16) float s1[E], s2[E];
    if (t < E) s1[t] = d_q1[b * E + t];
    else if (t < 2 * E) s2[t - E] = d_q2[b * E + t - E];
    __syncthreads();
    int j = t >> 7, f = t & 127;
    const uint4* w = (const uint4*)(d_WQb + ((size_t)j * 128 + f) * 128);
    const float4* x = (const float4*)((j == 0 || j == 2) ? s1 : s2);
    float acc = 0.f;
#pragma unroll 4
    for (int e8 = 0; e8 < E / 8; e8++) {
        uint4 wa = w[e8];
        DOT8(acc, wa, x + e8 * 2);
    }
    d_Qp[((size_t)iter * BS + b) * 512 + t] = acc;
}

// ---------------- mega score: ONE pass over Kc computes all 4 iterations ----------------
// grid (BS, 125), 256 threads; each warp handles 2 g-rows.
__global__ void __launch_bounds__(256) mega_score_kernel(const int* __restrict__ last_action,
                                                         const float* __restrict__ V1,
                                                         const float* __restrict__ V2) {
    int b = blockIdx.x, t = threadIdx.x;
    int warp = t >> 5, lane = t & 31;
    __shared__ float sQ[KM][512];
    __shared__ float sV[256];
    __shared__ float sE[KM][8];
#pragma unroll
    for (int it = 0; it < KM; it++) {
        sQ[it][t] = d_Qp[((size_t)it * BS + b) * 512 + t];
        sQ[it][256 + t] = d_Qp[((size_t)it * BS + b) * 512 + 256 + t];
    }
    sV[t] = (t < 128) ? V1[t] : V2[t - 128];
    __syncthreads();

    int g0 = blockIdx.y * 16 + warp * 2;
    const unsigned char* __restrict__ Kc = d_Kc8 + ((size_t)b * GS + g0) * 512;
    int f0 = lane * 4;
    unsigned ua1 = *(const unsigned*)(Kc + f0);
    unsigned ua2 = *(const unsigned*)(Kc + 128 + f0);
    unsigned ua3 = *(const unsigned*)(Kc + 256 + f0);
    unsigned ua4 = *(const unsigned*)(Kc + 384 + f0);
    unsigned ub1 = *(const unsigned*)(Kc + 512 + f0);
    unsigned ub2 = *(const unsigned*)(Kc + 640 + f0);
    unsigned ub3 = *(const unsigned*)(Kc + 768 + f0);
    unsigned ub4 = *(const unsigned*)(Kc + 896 + f0);

    float ka1[4], ka2[4], ka3[4], ka4[4];
    float kb1[4], kb2[4], kb3[4], kb4[4];
    fp8x4_to_f32(ua1, ka1); fp8x4_to_f32(ua2, ka2);
    fp8x4_to_f32(ua3, ka3); fp8x4_to_f32(ua4, ka4);
    fp8x4_to_f32(ub1, kb1); fp8x4_to_f32(ub2, kb2);
    fp8x4_to_f32(ub3, kb3); fp8x4_to_f32(ub4, kb4);

    int v0 = 0, v1 = 0, la = 0;
    if (lane == 0) {
        v0 = d_vtt[b * GS + g0];
        v1 = d_vtt[b * GS + g0 + 1];
        la = last_action[b];
    }

#pragma unroll
    for (int it = 0; it < KM; it++) {
        float s0 = 0.f, s1 = 0.f;
#pragma unroll
        for (int i = 0; i < 4; i++) {
            int f = f0 + i;
            float q0v = sQ[it][f], q1v = sQ[it][128 + f];
            float q2v = sQ[it][256 + f], q3v = sQ[it][384 + f];
            s0 = fmaf(sV[f], tanh_fast(fmaf(ka3[i], q2v, ka1[i] + q0v)), s0);
            s0 = fmaf(sV[128 + f], tanh_fast(fmaf(ka4[i], q3v, ka2[i] + q1v)), s0);
            s1 = fmaf(sV[f], tanh_fast(fmaf(kb3[i], q2v, kb1[i] + q0v)), s1);
            s1 = fmaf(sV[128 + f], tanh_fast(fmaf(kb4[i], q3v, kb2[i] + q1v)), s1);
        }
#pragma unroll
        for (int o = 16; o; o >>= 1) {
            s0 += __shfl_xor_sync(0xFFFFFFFFu, s0, o);
            s1 += __shfl_xor_sync(0xFFFFFFFFu, s1, o);
        }
        if (lane == 0) {
            float lg0 = tanhf(s0) * CLIPV;
            float lg1 = tanhf(s1) * CLIPV;
            bool m0, m1;
            if (it == 0) {
                m0 = (g0 == la); m1 = (g0 + 1 == la);
            } else {
                int mva  = d_mva[it * BS + b];
                int msn  = d_mstopnew[it * BS + b];
                int mact = d_mact[it * BS + b];
                int mal  = d_mallow[it * BS + b];
                int mai0 = d_mai0[it * BS + b];
                m0 = (v0 <= mva); m1 = (v1 <= mva);
                if (it == 1) { m0 = m0 || (v0 > GS - 2); m1 = m1 || (v1 > GS - 2); }
                if (msn) { if (g0 == mact) m0 = false; if (g0 + 1 == mact) m1 = false; }
                if (mal) { if (g0 == mai0) m0 = false; if (g0 + 1 == mai0) m1 = false; }
            }
            int act = d_gact[it * BS + b];
            if (g0 == act)     d_logact4[it * BS + b] = m0 ? NEGV : lg0;
            if (g0 + 1 == act) d_logact4[it * BS + b] = m1 ? NEGV : lg1;
            sE[it][warp] = (m0 ? 0.f : expf(lg0 - CLIPV)) + (m1 ? 0.f : expf(lg1 - CLIPV));
        }
    }
    __syncthreads();
    if (t < KM) {
        float e = 0.f;
#pragma unroll
        for (int i = 0; i < 8; i++) e += sE[t][i];
        atomicAdd(&d_expsum4[t * BS + b], e);
    }
}

// ---------------- loss epilogue (one thread per b) ----------------
__global__ void loss_kernel() {
    int b = threadIdx.x;          // <<<1,128>>>
    if (b >= BS) return;
    float ll = 0.f;
#pragma unroll
    for (int it = 0; it < KM; it++) {
        float es = d_expsum4[it * BS + b];
        // es == 0 exactly <=> ALL logits masked -> logp[action] = -log(GS)
        float loss = (es > 0.0f) ? (d_logact4[it * BS + b] - (CLIPV + logf(es)))
                                 : (-logf((float)GS));
        if (it == 0 || !d_gstopold[it * BS + b]) ll += loss;
    }
    d_ll[b] = ll;
}

// ---------------- output ----------------
__global__ void out_kernel(float* __restrict__ out) {
    int idx = blockIdx.x * 256 + threadIdx.x;
    if (idx < BS * 12) {
        int b = idx / 12, j = idx % 12;
        int v;
        if (j < 4) v = d_ai[b * 4 + j];
        else if (j < 8) v = d_kl[b * 5 + (j - 4)];
        else {
            int jj = j - 8;
            if (jj == 3 && !d_stopped[b]) v = d_kl[b * 5 + 4];  // post-loop kr fix
            else v = d_kr[b * 4 + jj];
        }
        out[idx] = (float)v;
    } else if (idx < BS * 12 + BS) {
        out[idx] = d_ll[idx - BS * 12];
    }
}

// ---------------- launch ----------------
extern "C" void kernel_launch(void* const* d_in, const int* in_sizes, int n_in,
                              void* d_out, int out_size) {
    (void)in_sizes; (void)n_in; (void)out_size;
    const float* h            = (const float*)d_in[0];
    const int*   rec          = (const int*)  d_in[1];
    /* context2 d_in[2] unused */
    const int*   visited_time = (const int*)  d_in[3];
    const int*   last_action  = (const int*)  d_in[4];
    const int*   fixed_action = (const int*)  d_in[5];
    const float* W_K1 = (const float*)d_in[6];
    const float* W_K2 = (const float*)d_in[7];
    const float* W_K3 = (const float*)d_in[8];
    const float* W_K4 = (const float*)d_in[9];
    const float* W_Q1 = (const float*)d_in[10];
    const float* W_Q2 = (const float*)d_in[11];
    const float* W_Q3 = (const float*)d_in[12];
    const float* W_Q4 = (const float*)d_in[13];
    const float* W_init     = (const float*)d_in[14];
    const float* b_init     = (const float*)d_in[15];
    const float* V1         = (const float*)d_in[16];
    const float* V2         = (const float*)d_in[17];
    const float* init_query = (const float*)d_in[18];
    const float* r1_Wih = (const float*)d_in[19];
    const float* r1_Whh = (const float*)d_in[20];
    const float* r1_bih = (const float*)d_in[21];
    const float* r1_bhh = (const float*)d_in[22];
    const float* r2_Wih = (const float*)d_in[23];
    const float* r2_Whh = (const float*)d_in[24];
    const float* r2_bih = (const float*)d_in[25];
    const float* r2_bhh = (const float*)d_in[26];

    static int smem_set = 0;
    if (!smem_set) {
        cudaFuncSetAttribute(gemm_kernel, cudaFuncAttributeMaxDynamicSharedMemorySize,
                             GEMM_SMEM);
        smem_set = 1;
    }

    convert_w<<<256, 256>>>(W_K1, W_K2, W_K3, W_K4);
    convert_wsmall<<<1024, 256>>>(r1_Wih, r1_Whh, r2_Wih, r2_Whh,
                                  W_Q1, W_Q2, W_Q3, W_Q4);
    hmean_kernel<<<BS, 512>>>(h);
    vtt_kernel<<<BS, 256>>>(visited_time, fixed_action);
    init_kernel<<<BS, 128>>>(W_init, b_init);
    precompute_kernel<<<1, 128>>>(rec, fixed_action);
    gemm_kernel<<<dim3(8, 2000), 256, GEMM_SMEM>>>();

    for (int i = 0; i < KM; i++) {
        gru_kernel<<<dim3(BS, 2), 384>>>(i, h, init_query,
                                         r1_bih, r1_bhh, r2_bih, r2_bhh);
        qproj_kernel<<<BS, 512>>>(i);
    }
    mega_score_kernel<<<dim3(BS, 125), 256>>>(last_action, V1, V2);
    loss_kernel<<<1, 128>>>();
    out_kernel<<<7, 256>>>((float*)d_out);
}

// round 15
// speedup vs baseline: 2.4184x; 1.1576x over previous
#include <cuda_runtime.h>
#include <cuda_bf16.h>
#include <cuda_fp16.h>
#include <math.h>
#include <stdint.h>

#define BS   128
#define GS   2000
#define E    128
#define KM   4
#define NEGV (-1.0e30f)
#define CLIPV 10.0f

// ---------------- device scratch (static globals; no runtime allocation) ----------------
__device__ unsigned char d_Kc8[(size_t)BS * GS * 512];  // [b][g][K1|K2|K3|K4] e4m3 (131 MB)
__device__ __nv_bfloat16 d_hb[(size_t)BS * GS * E];     // bf16 copy of h (65 MB)
__device__ __nv_bfloat16 d_Wb[512 * 128];               // [n=j*128+f][k=e] bf16 (col-major B)
__device__ __nv_bfloat16 d_Wgb[4 * 384 * 128];          // r1_Wih|r1_Whh|r2_Wih|r2_Whh bf16
__device__ __nv_bfloat16 d_WQb[4 * 128 * 128];          // WQ1..WQ4 bf16
__device__ int   d_vtt[BS * GS];
__device__ float d_q1[BS * E], d_q2[BS * E];
__device__ float d_Qp[(size_t)KM * BS * 512];           // [iter][b][Q1|Q2|Q3|Q4]
__device__ float d_hmean[BS * E];
__device__ int   d_ai[BS * 4];
__device__ int   d_kl[BS * 5];
__device__ int   d_kr[BS * 4];
__device__ int   d_stopped[BS];
// precomputed per-iteration scalars
__device__ int   d_gact[KM * BS];
__device__ int   d_gstopold[KM * BS];
__device__ int   d_gnolmod[KM * BS];
__device__ int   d_mva[KM * BS];
__device__ int   d_mstopnew[KM * BS];
__device__ int   d_mact[KM * BS];
__device__ int   d_mallow[KM * BS];
__device__ int   d_mai0[KM * BS];
__device__ float d_expsum4[KM * BS];
__device__ float d_logact4[KM * BS];

// ---------------- math helpers ----------------
__device__ __forceinline__ float fast_rcp(float x) {
    float r = __uint_as_float(0x7EF311C3u - __float_as_uint(x));
    r = r * (2.0f - x * r);
    r = r * (2.0f - x * r);
    return r;
}
__device__ __forceinline__ float tanh_fast(float x) {
    float xc = fminf(fmaxf(x, -3.6f), 3.6f);
    float x2 = xc * xc;
    float num = xc * fmaf(x2, x2 + 105.0f, 945.0f);
    float den = fmaf(x2, fmaf(15.0f, x2, 420.0f), 945.0f);
    return num * fast_rcp(den);
}
__device__ __forceinline__ float sigmoidf_(float x) { return 1.0f / (1.0f + expf(-x)); }

__device__ __forceinline__ unsigned short fp8pack(float a, float b) {
    unsigned short p;
    asm("cvt.rn.satfinite.e4m3x2.f32 %0, %1, %2;" : "=h"(p) : "f"(b), "f"(a));
    return p;
}
// 4 e4m3 bytes -> two half2 (native conversion; lo = bytes0,1)
__device__ __forceinline__ void fp8x4_to_h2(unsigned u, __half2& lo, __half2& hi) {
    unsigned h01, h23;
    asm("{\n\t.reg .b16 a, b;\n\t"
        "mov.b32 {a, b}, %2;\n\t"
        "cvt.rn.f16x2.e4m3x2 %0, a;\n\t"
        "cvt.rn.f16x2.e4m3x2 %1, b;\n\t}"
        : "=r"(h01), "=r"(h23) : "r"(u));
    lo = *reinterpret_cast<__half2*>(&h01);
    hi = *reinterpret_cast<__half2*>(&h23);
}
__device__ __forceinline__ float2 bf2f(unsigned u) {
    return __bfloat1622float2(*reinterpret_cast<__nv_bfloat162*>(&u));
}
__device__ __forceinline__ void cp_async16(void* smem_dst, const void* gsrc) {
    unsigned daddr = (unsigned)__cvta_generic_to_shared(smem_dst);
    asm volatile("cp.async.cg.shared.global [%0], [%1], 16;" :: "r"(daddr), "l"(gsrc) : "memory");
}

// half2 Pade(5,4) tanh; den in [945, ~8910] -> bit-hack rcp seed (<=6% err) + 2 Newton
__device__ __forceinline__ __half2 tanh_h2(__half2 x) {
    const __half2 c36  = __floats2half2_rn(3.6f, 3.6f);
    const __half2 c105 = __floats2half2_rn(105.f, 105.f);
    const __half2 c945 = __floats2half2_rn(945.f, 945.f);
    const __half2 c420 = __floats2half2_rn(420.f, 420.f);
    const __half2 c15  = __floats2half2_rn(15.f, 15.f);
    const __half2 two  = __floats2half2_rn(2.f, 2.f);
    x = __hmin2(__hmax2(x, __hneg2(c36)), c36);
    __half2 x2 = __hmul2(x, x);
    __half2 num = __hmul2(x, __hfma2(x2, __hadd2(x2, c105), c945));
    __half2 den = __hfma2(x2, __hfma2(c15, x2, c420), c945);
    unsigned db = *reinterpret_cast<unsigned*>(&den);
    unsigned rb = 0x77807780u - db;              // den bits <= 0x7059: no lane borrow
    __half2 r = *reinterpret_cast<__half2*>(&rb);
    r = __hmul2(r, __hsub2(two, __hmul2(den, r)));
    r = __hmul2(r, __hsub2(two, __hmul2(den, r)));
    return __hmul2(num, r);
}

#define LDSM4(r, addr) \
    asm volatile("ldmatrix.sync.aligned.m8n8.x4.shared.b16 {%0,%1,%2,%3}, [%4];" \
                 : "=r"((r)[0]), "=r"((r)[1]), "=r"((r)[2]), "=r"((r)[3]) : "r"(addr))

#define MMA16816(c, a, b0, b1) \
    asm volatile("mma.sync.aligned.m16n8k16.row.col.f32.bf16.bf16.f32 " \
                 "{%0,%1,%2,%3},{%4,%5,%6,%7},{%8,%9},{%0,%1,%2,%3};" \
                 : "+f"((c)[0]), "+f"((c)[1]), "+f"((c)[2]), "+f"((c)[3]) \
                 : "r"((a)[0]), "r"((a)[1]), "r"((a)[2]), "r"((a)[3]), "r"(b0), "r"(b1))

#define DOT8(acc, w4, xp)                                            \
    do {                                                             \
        float2 _p; float4 _x0 = (xp)[0], _x1 = (xp)[1];              \
        _p = bf2f((w4).x); acc = fmaf(_p.x, _x0.x, acc); acc = fmaf(_p.y, _x0.y, acc); \
        _p = bf2f((w4).y); acc = fmaf(_p.x, _x0.z, acc); acc = fmaf(_p.y, _x0.w, acc); \
        _p = bf2f((w4).z); acc = fmaf(_p.x, _x1.x, acc); acc = fmaf(_p.y, _x1.y, acc); \
        _p = bf2f((w4).w); acc = fmaf(_p.x, _x1.z, acc); acc = fmaf(_p.y, _x1.w, acc); \
    } while (0)

// ---------------- setup kernels ----------------
__global__ void convert_w(const float* __restrict__ W1, const float* __restrict__ W2,
                          const float* __restrict__ W3, const float* __restrict__ W4) {
    int idx = blockIdx.x * blockDim.x + threadIdx.x;
    if (idx >= 512 * 128) return;
    int j = idx >> 14, r = idx & 16383;
    const float* W = (j == 0) ? W1 : (j == 1) ? W2 : (j == 2) ? W3 : W4;
    d_Wb[idx] = __float2bfloat16(W[r]);
}

__global__ void convert_wsmall(const float* __restrict__ g0, const float* __restrict__ g1,
                               const float* __restrict__ g2, const float* __restrict__ g3,
                               const float* __restrict__ q0, const float* __restrict__ q1,
                               const float* __restrict__ q2, const float* __restrict__ q3) {
    int idx = blockIdx.x * blockDim.x + threadIdx.x;
    if (idx < 4 * 49152) {
        int m = idx / 49152, r = idx % 49152;
        const float* W = (m == 0) ? g0 : (m == 1) ? g1 : (m == 2) ? g2 : g3;
        d_Wgb[idx] = __float2bfloat16(W[r]);
    } else if (idx < 4 * 49152 + 4 * 16384) {
        int k = idx - 4 * 49152;
        int m = k / 16384, r = k % 16384;
        const float* W = (m == 0) ? q0 : (m == 1) ? q1 : (m == 2) ? q2 : q3;
        d_WQb[k] = __float2bfloat16(W[r]);
    }
}

__global__ void hmean_kernel(const float* __restrict__ h) {
    int b = blockIdx.x, t = threadIdx.x;                 // 512 threads
    int e = t & 127, q = t >> 7;
    __shared__ float part[4][128];
    float s = 0.f;
    for (int g = q * 500; g < (q + 1) * 500; g++) {
        size_t idx = ((size_t)b * GS + g) * E + e;
        float v = h[idx];
        s += v;
        d_hb[idx] = __float2bfloat16(v);
    }
    part[q][e] = s;
    __syncthreads();
    if (t < 128)
        d_hmean[b * E + t] = (part[0][t] + part[1][t] + part[2][t] + part[3][t]) * (1.0f / GS);
}

__global__ void vtt_kernel(const int* __restrict__ vt, const int* __restrict__ fixed_action) {
    int b = blockIdx.x, t = threadIdx.x;
    int bG = b * GS;
    int vta = vt[bG + fixed_action[b * KM]];
    for (int g = t; g < GS; g += 256) {
        int d = vt[bG + g] - vta;
        d_vtt[bG + g] = (d + GS) % GS;                   // Python floored mod
    }
}

__global__ void init_kernel(const float* __restrict__ W_init, const float* __restrict__ b_init) {
    int b = blockIdx.x, t = threadIdx.x;                 // 128 threads
    __shared__ __align__(16) float sm[E];
    sm[t] = d_hmean[b * E + t];
    __syncthreads();
    float acc = b_init[t];
    const float4* w = (const float4*)(W_init + t * E);
    const float4* x = (const float4*)sm;
#pragma unroll 8
    for (int e4 = 0; e4 < E / 4; e4++) {
        float4 a = w[e4], v = x[e4];
        acc = fmaf(a.x, v.x, acc); acc = fmaf(a.y, v.y, acc);
        acc = fmaf(a.z, v.z, acc); acc = fmaf(a.w, v.w, acc);
    }
    d_q1[b * E + t] = acc;
    d_q2[b * E + t] = acc;
}

// ---- full 4-iteration integer bookkeeping simulation (one thread per b) ----
__global__ void precompute_kernel(const int* __restrict__ rec,
                                  const int* __restrict__ fixed_action) {
    int b = threadIdx.x;          // <<<1,128>>>
    if (b >= BS) return;
    const int bG = b * GS;
    int stopped = 1, nol = -1;
    int ai[4] = {0, 0, 0, 0};
    int kl[5] = {0, 0, 0, 0, 0};
    int kr[4] = {0, 0, 0, 0};
#pragma unroll
    for (int i = 0; i < KM; i++) {
        int stop_old = stopped;
        int action = (i > 0 && stop_old) ? ai[0] : fixed_action[b * KM + i];

        d_gact[i * BS + b] = action;
        d_gstopold[i * BS + b] = stop_old;
        d_gnolmod[i * BS + b] = ((nol % GS) + GS) % GS;

        int nna = rec[bG + action];
        ai[i] = action;
        if (stop_old) kl[i] = action;
        int krm1 = ((i - 1) + KM) % KM;
        if (!stop_old) kr[krm1] = action;
        kl[i + 1] = nna;

        int eq = (action == nol) ? 1 : 0;
        int stop_new = (i == 0) ? eq : (stop_old | eq);
        if (stop_new) {
            kl[i] = kl[((i - 1) + 5) % 5];
            kr[i] = kr[krm1];
        }
        stopped = stop_new;
        nol = stop_new ? -1 : nna;
        int ai0 = ai[0];

        if (i + 1 < KM) {
            d_mva[(i + 1) * BS + b] = d_vtt[bG + action];
            d_mstopnew[(i + 1) * BS + b] = stop_new;
            d_mact[(i + 1) * BS + b] = action;
            d_mallow[(i + 1) * BS + b] = (!stop_new && nna == ai0) ? 1 : 0;
            d_mai0[(i + 1) * BS + b] = ai0;
        }
        d_expsum4[i * BS + b] = 0.0f;
    }
#pragma unroll
    for (int i = 0; i < 4; i++) d_ai[b * 4 + i] = ai[i];
#pragma unroll
    for (int i = 0; i < 5; i++) d_kl[b * 5 + i] = kl[i];
#pragma unroll
    for (int i = 0; i < 4; i++) d_kr[b * 4 + i] = kr[i];
    d_stopped[b] = stopped;
}

// ---------------- bf16 MMA GEMM: Kc8 = e4m3(hb @ W^T) ---------------- (r13, unchanged)
#define GEMM_SMEM ((128 * 136 + 64 * 136) * 2)
__global__ void __launch_bounds__(256) gemm_kernel() {
    extern __shared__ __align__(16) char smem_raw[];
    __nv_bfloat16 (*As)[136] = (__nv_bfloat16(*)[136])smem_raw;
    __nv_bfloat16 (*Bs)[136] = (__nv_bfloat16(*)[136])(smem_raw + 128 * 136 * 2);
    const int t = threadIdx.x;
    const int warp = t >> 5, lane = t & 31;
    const int n0 = blockIdx.x * 64, m0 = blockIdx.y * 128;
    const int wm = (warp >> 1) * 32, wn = (warp & 1) * 32;

#pragma unroll
    for (int i = t; i < 128 * 16; i += 256) {
        int row = i >> 4, c8 = i & 15;
        cp_async16(&As[row][c8 * 8], d_hb + (size_t)(m0 + row) * 128 + c8 * 8);
    }
#pragma unroll
    for (int i = t; i < 64 * 16; i += 256) {
        int n = i >> 4, c8 = i & 15;
        cp_async16(&Bs[n][c8 * 8], d_Wb + (size_t)(n0 + n) * 128 + c8 * 8);
    }
    asm volatile("cp.async.commit_group;\ncp.async.wait_group 0;" ::: "memory");
    __syncthreads();

    float c[2][4][4];
#pragma unroll
    for (int i = 0; i < 2; i++)
#pragma unroll
        for (int j = 0; j < 4; j++)
#pragma unroll
            for (int k = 0; k < 4; k++) c[i][j][k] = 0.f;

    const int a_row = (lane & 15), a_colh = (lane >> 4) * 8;
    const int b_row = ((lane >> 4) & 1) * 8 + (lane & 7);
    const int b_colh = ((lane >> 3) & 1) * 8;

    unsigned a_addr0 = (unsigned)__cvta_generic_to_shared(&As[wm + a_row][a_colh]);
    unsigned a_addr1 = (unsigned)__cvta_generic_to_shared(&As[wm + 16 + a_row][a_colh]);
    unsigned b_addr0 = (unsigned)__cvta_generic_to_shared(&Bs[wn + b_row][b_colh]);
    unsigned b_addr1 = (unsigned)__cvta_generic_to_shared(&Bs[wn + 16 + b_row][b_colh]);

#pragma unroll
    for (int ks = 0; ks < 8; ks++) {
        unsigned koff = ks * 32;
        unsigned af0[4], af1[4], bf0[4], bf1[4];
        LDSM4(af0, a_addr0 + koff);
        LDSM4(af1, a_addr1 + koff);
        LDSM4(bf0, b_addr0 + koff);
        LDSM4(bf1, b_addr1 + koff);
        MMA16816(c[0][0], af0, bf0[0], bf0[1]);
        MMA16816(c[0][1], af0, bf0[2], bf0[3]);
        MMA16816(c[0][2], af0, bf1[0], bf1[1]);
        MMA16816(c[0][3], af0, bf1[2], bf1[3]);
        MMA16816(c[1][0], af1, bf0[0], bf0[1]);
        MMA16816(c[1][1], af1, bf0[2], bf0[3]);
        MMA16816(c[1][2], af1, bf1[0], bf1[1]);
        MMA16816(c[1][3], af1, bf1[2], bf1[3]);
    }

    const int qr = lane >> 2, qc = lane & 3;
#pragma unroll
    for (int mf = 0; mf < 2; mf++)
#pragma unroll
        for (int nf = 0; nf < 4; nf++) {
            int row = m0 + wm + mf * 16 + qr;
            int col = n0 + wn + nf * 8 + qc * 2;
            unsigned short p0 = fp8pack(c[mf][nf][0], c[mf][nf][1]);
            unsigned short p1 = fp8pack(c[mf][nf][2], c[mf][nf][3]);
            *(unsigned short*)(d_Kc8 + (size_t)row * 512 + col) = p0;
            *(unsigned short*)(d_Kc8 + (size_t)(row + 8) * 512 + col) = p1;
        }
}

// ---------------- fused GRU chain + Q projections: all 4 iterations, one launch ----------------
// grid (BS, 2): r=0 does q1 chain + WQ1/WQ3 projections; r=1 does q2 chain + WQ2/WQ4.
__global__ void __launch_bounds__(384) gruchain_kernel(
    const float* __restrict__ h, const float* __restrict__ init_query,
    const float* __restrict__ bih1, const float* __restrict__ bhh1,
    const float* __restrict__ bih2, const float* __restrict__ bhh2) {
    int b = blockIdx.x, r = blockIdx.y, t = threadIdx.x;   // 384 threads
    const float* bih = r ? bih2 : bih1;
    const float* bhh = r ? bhh2 : bhh1;

    __shared__ __align__(16) float sx[E], sq[E];
    __shared__ float gi[3 * E], gh[3 * E];
    if (t < E) sq[t] = (r ? d_q2 : d_q1)[b * E + t];

    const uint4* wi = (const uint4*)(d_Wgb + ((size_t)(r * 2) * 384 + t) * 128);
    const uint4* wh = (const uint4*)(d_Wgb + ((size_t)(r * 2 + 1) * 384 + t) * 128);

    for (int it = 0; it < KM; it++) {
        if (t < E) {
            float x;
            if (it == 0) {
                x = init_query[t];
            } else {
                int idx = (it - 1) * BS + b;
                int act = d_gact[idx];
                int gg = (r == 0) ? act : (d_gstopold[idx] ? act : d_gnolmod[idx]);
                x = h[((size_t)b * GS + gg) * E + t];
            }
            sx[t] = x;
        }
        __syncthreads();   // sx ready; also orders prev-iter qproj reads before gate write

        float a = bih[t], cg = bhh[t];
        const float4* x4 = (const float4*)sx;
        const float4* h4 = (const float4*)sq;
#pragma unroll 4
        for (int e8 = 0; e8 < E / 8; e8++) {
            uint4 wa = wi[e8], wb = wh[e8];
            DOT8(a, wa, x4 + e8 * 2);
            DOT8(cg, wb, h4 + e8 * 2);
        }
        gi[t] = a; gh[t] = cg;
        __syncthreads();

        if (t < E) {
            float rr = sigmoidf_(gi[t] + gh[t]);
            float z  = sigmoidf_(gi[E + t] + gh[E + t]);
            float n  = tanhf(gi[2 * E + t] + rr * gh[2 * E + t]);
            sq[t] = (1.0f - z) * n + z * sq[t];
        }
        __syncthreads();   // sq ready for qproj

        if (t < 256) {
            int jj = t >> 7, f = t & 127;
            int j = (r == 0) ? (jj ? 2 : 0) : (jj ? 3 : 1);
            const uint4* w = (const uint4*)(d_WQb + ((size_t)j * 128 + f) * 128);
            const float4* x = (const float4*)sq;
            float acc = 0.f;
#pragma unroll 4
            for (int e8 = 0; e8 < E / 8; e8++) {
                uint4 wa = w[e8];
                DOT8(acc, wa, x + e8 * 2);
            }
            d_Qp[((size_t)it * BS + b) * 512 + j * 128 + f] = acc;
        }
    }
}

// ---------------- mega score (half2 datapath): ONE pass over Kc, all 4 iterations ----------------
// grid (BS, 125), 256 threads; each warp handles 2 g-rows.
__global__ void __launch_bounds__(256) mega_score_kernel(const int* __restrict__ last_action,
                                                         const float* __restrict__ V1,
                                                         const float* __restrict__ V2) {
    int b = blockIdx.x, t = threadIdx.x;
    int warp = t >> 5, lane = t & 31;
    __shared__ __half2 sQh[KM][4][64];   // [iter][seg][fpair]
    __shared__ __half2 sVh[2][64];
    __shared__ float sE[KM][8];
    for (int i = t; i < KM * 256; i += 256) {
        int it = i >> 8, rem = i & 255;
        int seg = rem >> 6, f2 = rem & 63;
        const float* qp = d_Qp + ((size_t)it * BS + b) * 512 + seg * 128 + f2 * 2;
        sQh[it][seg][f2] = __floats2half2_rn(qp[0], qp[1]);
    }
    if (t < 128) {
        int seg = t >> 6, f2 = t & 63;
        const float* V = seg ? V2 : V1;
        sVh[seg][f2] = __floats2half2_rn(V[f2 * 2], V[f2 * 2 + 1]);
    }
    __syncthreads();

    int g0 = blockIdx.y * 16 + warp * 2;
    const unsigned char* __restrict__ Kc = d_Kc8 + ((size_t)b * GS + g0) * 512;
    int f0 = lane * 4;
    unsigned ua1 = *(const unsigned*)(Kc + f0);
    unsigned ua2 = *(const unsigned*)(Kc + 128 + f0);
    unsigned ua3 = *(const unsigned*)(Kc + 256 + f0);
    unsigned ua4 = *(const unsigned*)(Kc + 384 + f0);
    unsigned ub1 = *(const unsigned*)(Kc + 512 + f0);
    unsigned ub2 = *(const unsigned*)(Kc + 640 + f0);
    unsigned ub3 = *(const unsigned*)(Kc + 768 + f0);
    unsigned ub4 = *(const unsigned*)(Kc + 896 + f0);

    __half2 k1h[2], k2h[2], k3h[2], k4h[2];   // row a
    __half2 l1h[2], l2h[2], l3h[2], l4h[2];   // row b
    fp8x4_to_h2(ua1, k1h[0], k1h[1]); fp8x4_to_h2(ua2, k2h[0], k2h[1]);
    fp8x4_to_h2(ua3, k3h[0], k3h[1]); fp8x4_to_h2(ua4, k4h[0], k4h[1]);
    fp8x4_to_h2(ub1, l1h[0], l1h[1]); fp8x4_to_h2(ub2, l2h[0], l2h[1]);
    fp8x4_to_h2(ub3, l3h[0], l3h[1]); fp8x4_to_h2(ub4, l4h[0], l4h[1]);

    int v0 = 0, v1 = 0, la = 0;
    if (lane == 0) {
        v0 = d_vtt[b * GS + g0];
        v1 = d_vtt[b * GS + g0 + 1];
        la = last_action[b];
    }

#pragma unroll
    for (int it = 0; it < KM; it++) {
        __half2 accA = __floats2half2_rn(0.f, 0.f);
        __half2 accB = __floats2half2_rn(0.f, 0.f);
#pragma unroll
        for (int ii = 0; ii < 2; ii++) {
            int p = lane * 2 + ii;
            __half2 q0 = sQh[it][0][p], q1 = sQh[it][1][p];
            __half2 q2 = sQh[it][2][p], q3 = sQh[it][3][p];
            __half2 vv1 = sVh[0][p], vv2 = sVh[1][p];
            accA = __hfma2(vv1, tanh_h2(__hfma2(k3h[ii], q2, __hadd2(k1h[ii], q0))), accA);
            accA = __hfma2(vv2, tanh_h2(__hfma2(k4h[ii], q3, __hadd2(k2h[ii], q1))), accA);
            accB = __hfma2(vv1, tanh_h2(__hfma2(l3h[ii], q2, __hadd2(l1h[ii], q0))), accB);
            accB = __hfma2(vv2, tanh_h2(__hfma2(l4h[ii], q3, __hadd2(l2h[ii], q1))), accB);
        }
        float2 fa = __half22float2(accA);
        float2 fb = __half22float2(accB);
        float s0 = fa.x + fa.y, s1 = fb.x + fb.y;
#pragma unroll
        for (int o = 16; o; o >>= 1) {
            s0 += __shfl_xor_sync(0xFFFFFFFFu, s0, o);
            s1 += __shfl_xor_sync(0xFFFFFFFFu, s1, o);
        }
        if (lane == 0) {
            float lg0 = tanh_fast(s0) * CLIPV;
            float lg1 = tanh_fast(s1) * CLIPV;
            bool m0, m1;
            if (it == 0) {
                m0 = (g0 == la); m1 = (g0 + 1 == la);
            } else {
                int mva  = d_mva[it * BS + b];
                int msn  = d_mstopnew[it * BS + b];
                int mact = d_mact[it * BS + b];
                int mal  = d_mallow[it * BS + b];
                int mai0 = d_mai0[it * BS + b];
                m0 = (v0 <= mva); m1 = (v1 <= mva);
                if (it == 1) { m0 = m0 || (v0 > GS - 2); m1 = m1 || (v1 > GS - 2); }
                if (msn) { if (g0 == mact) m0 = false; if (g0 + 1 == mact) m1 = false; }
                if (mal) { if (g0 == mai0) m0 = false; if (g0 + 1 == mai0) m1 = false; }
            }
            int act = d_gact[it * BS + b];
            if (g0 == act)     d_logact4[it * BS + b] = m0 ? NEGV : lg0;
            if (g0 + 1 == act) d_logact4[it * BS + b] = m1 ? NEGV : lg1;
            sE[it][warp] = (m0 ? 0.f : expf(lg0 - CLIPV)) + (m1 ? 0.f : expf(lg1 - CLIPV));
        }
    }
    __syncthreads();
    if (t < KM) {
        float e = 0.f;
#pragma unroll
        for (int i = 0; i < 8; i++) e += sE[t][i];
        atomicAdd(&d_expsum4[t * BS + b], e);
    }
}

// ---------------- output (loss folded in) ----------------
__global__ void out_kernel(float* __restrict__ out) {
    int idx = blockIdx.x * 256 + threadIdx.x;
    if (idx < BS * 12) {
        int b = idx / 12, j = idx % 12;
        int v;
        if (j < 4) v = d_ai[b * 4 + j];
        else if (j < 8) v = d_kl[b * 5 + (j - 4)];
        else {
            int jj = j - 8;
            if (jj == 3 && !d_stopped[b]) v = d_kl[b * 5 + 4];  // post-loop kr fix
            else v = d_kr[b * 4 + jj];
        }
        out[idx] = (float)v;
    } else if (idx < BS * 12 + BS) {
        int b = idx - BS * 12;
        float ll = 0.f;
#pragma unroll
        for (int it = 0; it < KM; it++) {
            float es = d_expsum4[it * BS + b];
            // es == 0 exactly <=> ALL logits masked -> logp[action] = -log(GS)
            float loss = (es > 0.0f) ? (d_logact4[it * BS + b] - (CLIPV + logf(es)))
                                     : (-logf((float)GS));
            if (it == 0 || !d_gstopold[it * BS + b]) ll += loss;
        }
        out[idx] = ll;
    }
}

// ---------------- launch ----------------
extern "C" void kernel_launch(void* const* d_in, const int* in_sizes, int n_in,
                              void* d_out, int out_size) {
    (void)in_sizes; (void)n_in; (void)out_size;
    const float* h            = (const float*)d_in[0];
    const int*   rec          = (const int*)  d_in[1];
    /* context2 d_in[2] unused */
    const int*   visited_time = (const int*)  d_in[3];
    const int*   last_action  = (const int*)  d_in[4];
    const int*   fixed_action = (const int*)  d_in[5];
    const float* W_K1 = (const float*)d_in[6];
    const float* W_K2 = (const float*)d_in[7];
    const float* W_K3 = (const float*)d_in[8];
    const float* W_K4 = (const float*)d_in[9];
    const float* W_Q1 = (const float*)d_in[10];
    const float* W_Q2 = (const float*)d_in[11];
    const float* W_Q3 = (const float*)d_in[12];
    const float* W_Q4 = (const float*)d_in[13];
    const float* W_init     = (const float*)d_in[14];
    const float* b_init     = (const float*)d_in[15];
    const float* V1         = (const float*)d_in[16];
    const float* V2         = (const float*)d_in[17];
    const float* init_query = (const float*)d_in[18];
    const float* r1_Wih = (const float*)d_in[19];
    const float* r1_Whh = (const float*)d_in[20];
    const float* r1_bih = (const float*)d_in[21];
    const float* r1_bhh = (const float*)d_in[22];
    const float* r2_Wih = (const float*)d_in[23];
    const float* r2_Whh = (const float*)d_in[24];
    const float* r2_bih = (const float*)d_in[25];
    const float* r2_bhh = (const float*)d_in[26];

    static int smem_set = 0;
    if (!smem_set) {
        cudaFuncSetAttribute(gemm_kernel, cudaFuncAttributeMaxDynamicSharedMemorySize,
                             GEMM_SMEM);
        smem_set = 1;
    }

    convert_w<<<256, 256>>>(W_K1, W_K2, W_K3, W_K4);
    convert_wsmall<<<1024, 256>>>(r1_Wih, r1_Whh, r2_Wih, r2_Whh,
                                  W_Q1, W_Q2, W_Q3, W_Q4);
    hmean_kernel<<<BS, 512>>>(h);
    vtt_kernel<<<BS, 256>>>(visited_time, fixed_action);
    init_kernel<<<BS, 128>>>(W_init, b_init);
    precompute_kernel<<<1, 128>>>(rec, fixed_action);
    gemm_kernel<<<dim3(8, 2000), 256, GEMM_SMEM>>>();
    gruchain_kernel<<<dim3(BS, 2), 384>>>(h, init_query,
                                          r1_bih, r1_bhh, r2_bih, r2_bhh);
    mega_score_kernel<<<dim3(BS, 125), 256>>>(last_action, V1, V2);
    out_kernel<<<7, 256>>>((float*)d_out);
}

// round 16
// speedup vs baseline: 2.4219x; 1.0015x over previous
#include <cuda_runtime.h>
#include <cuda_bf16.h>
#include <cuda_fp16.h>
#include <math.h>
#include <stdint.h>

#define BS   128
#define GS   2000
#define E    128
#define KM   4
#define NEGV (-1.0e30f)
#define CLIPV 10.0f

// ---------------- device scratch (static globals; no runtime allocation) ----------------
__device__ unsigned char d_Kc8[(size_t)BS * GS * 512];  // [b][g][K1|K2|K3|K4] e4m3 (131 MB)
__device__ __nv_bfloat16 d_hb[(size_t)BS * GS * E];     // bf16 copy of h (65 MB)
__device__ __nv_bfloat16 d_Wb[512 * 128];               // [n=j*128+f][k=e] bf16 (col-major B)
__device__ __nv_bfloat16 d_Wgb[4 * 384 * 128];          // r1_Wih|r1_Whh|r2_Wih|r2_Whh bf16
__device__ __nv_bfloat16 d_WQb[4 * 128 * 128];          // WQ1..WQ4 bf16
__device__ int   d_vtt[BS * GS];
__device__ float d_q1[BS * E], d_q2[BS * E];
__device__ float d_Qp[(size_t)KM * BS * 512];           // [iter][b][Q1|Q2|Q3|Q4]
__device__ float d_hmean[BS * E];
__device__ int   d_ai[BS * 4];
__device__ int   d_kl[BS * 5];
__device__ int   d_kr[BS * 4];
__device__ int   d_stopped[BS];
// precomputed per-iteration scalars
__device__ int   d_gact[KM * BS];
__device__ int   d_gstopold[KM * BS];
__device__ int   d_gnolmod[KM * BS];
__device__ int   d_mva[KM * BS];
__device__ int   d_mstopnew[KM * BS];
__device__ int   d_mact[KM * BS];
__device__ int   d_mallow[KM * BS];
__device__ int   d_mai0[KM * BS];
__device__ float d_expsum4[KM * BS];
__device__ float d_logact4[KM * BS];

// ---------------- math helpers ----------------
__device__ __forceinline__ float fast_rcp(float x) {
    float r = __uint_as_float(0x7EF311C3u - __float_as_uint(x));
    r = r * (2.0f - x * r);
    r = r * (2.0f - x * r);
    return r;
}
__device__ __forceinline__ float tanh_fast(float x) {
    float xc = fminf(fmaxf(x, -3.6f), 3.6f);
    float x2 = xc * xc;
    float num = xc * fmaf(x2, x2 + 105.0f, 945.0f);
    float den = fmaf(x2, fmaf(15.0f, x2, 420.0f), 945.0f);
    return num * fast_rcp(den);
}
__device__ __forceinline__ float sigmoidf_(float x) { return 1.0f / (1.0f + expf(-x)); }

__device__ __forceinline__ unsigned short fp8pack(float a, float b) {
    unsigned short p;
    asm("cvt.rn.satfinite.e4m3x2.f32 %0, %1, %2;" : "=h"(p) : "f"(b), "f"(a));
    return p;
}
// 4 e4m3 bytes -> two half2 (native conversion; lo = bytes0,1)
__device__ __forceinline__ void fp8x4_to_h2(unsigned u, __half2& lo, __half2& hi) {
    unsigned h01, h23;
    asm("{\n\t.reg .b16 a, b;\n\t"
        "mov.b32 {a, b}, %2;\n\t"
        "cvt.rn.f16x2.e4m3x2 %0, a;\n\t"
        "cvt.rn.f16x2.e4m3x2 %1, b;\n\t}"
        : "=r"(h01), "=r"(h23) : "r"(u));
    lo = *reinterpret_cast<__half2*>(&h01);
    hi = *reinterpret_cast<__half2*>(&h23);
}
__device__ __forceinline__ float2 bf2f(unsigned u) {
    return __bfloat1622float2(*reinterpret_cast<__nv_bfloat162*>(&u));
}
__device__ __forceinline__ void cp_async16(void* smem_dst, const void* gsrc) {
    unsigned daddr = (unsigned)__cvta_generic_to_shared(smem_dst);
    asm volatile("cp.async.cg.shared.global [%0], [%1], 16;" :: "r"(daddr), "l"(gsrc) : "memory");
}

// half2 Pade(5,4) tanh; den in [945, ~8910] -> bit-hack rcp seed + 2 Newton
__device__ __forceinline__ __half2 tanh_h2(__half2 x) {
    const __half2 c36  = __floats2half2_rn(3.6f, 3.6f);
    const __half2 c105 = __floats2half2_rn(105.f, 105.f);
    const __half2 c945 = __floats2half2_rn(945.f, 945.f);
    const __half2 c420 = __floats2half2_rn(420.f, 420.f);
    const __half2 c15  = __floats2half2_rn(15.f, 15.f);
    const __half2 two  = __floats2half2_rn(2.f, 2.f);
    x = __hmin2(__hmax2(x, __hneg2(c36)), c36);
    __half2 x2 = __hmul2(x, x);
    __half2 num = __hmul2(x, __hfma2(x2, __hadd2(x2, c105), c945));
    __half2 den = __hfma2(x2, __hfma2(c15, x2, c420), c945);
    unsigned db = *reinterpret_cast<unsigned*>(&den);
    unsigned rb = 0x77807780u - db;              // den bits <= 0x7059: no lane borrow
    __half2 r = *reinterpret_cast<__half2*>(&rb);
    r = __hmul2(r, __hsub2(two, __hmul2(den, r)));
    r = __hmul2(r, __hsub2(two, __hmul2(den, r)));
    return __hmul2(num, r);
}

#define LDSM4(r, addr) \
    asm volatile("ldmatrix.sync.aligned.m8n8.x4.shared.b16 {%0,%1,%2,%3}, [%4];" \
                 : "=r"((r)[0]), "=r"((r)[1]), "=r"((r)[2]), "=r"((r)[3]) : "r"(addr))

#define MMA16816(c, a, b0, b1) \
    asm volatile("mma.sync.aligned.m16n8k16.row.col.f32.bf16.bf16.f32 " \
                 "{%0,%1,%2,%3},{%4,%5,%6,%7},{%8,%9},{%0,%1,%2,%3};" \
                 : "+f"((c)[0]), "+f"((c)[1]), "+f"((c)[2]), "+f"((c)[3]) \
                 : "r"((a)[0]), "r"((a)[1]), "r"((a)[2]), "r"((a)[3]), "r"(b0), "r"(b1))

#define DOT8(acc, w4, xp)                                            \
    do {                                                             \
        float2 _p; float4 _x0 = (xp)[0], _x1 = (xp)[1];              \
        _p = bf2f((w4).x); acc = fmaf(_p.x, _x0.x, acc); acc = fmaf(_p.y, _x0.y, acc); \
        _p = bf2f((w4).y); acc = fmaf(_p.x, _x0.z, acc); acc = fmaf(_p.y, _x0.w, acc); \
        _p = bf2f((w4).z); acc = fmaf(_p.x, _x1.x, acc); acc = fmaf(_p.y, _x1.y, acc); \
        _p = bf2f((w4).w); acc = fmaf(_p.x, _x1.z, acc); acc = fmaf(_p.y, _x1.w, acc); \
    } while (0)

// ---------------- setup kernels ----------------
__global__ void convert_w(const float* __restrict__ W1, const float* __restrict__ W2,
                          const float* __restrict__ W3, const float* __restrict__ W4) {
    int idx = blockIdx.x * blockDim.x + threadIdx.x;
    if (idx >= 512 * 128) return;
    int j = idx >> 14, r = idx & 16383;
    const float* W = (j == 0) ? W1 : (j == 1) ? W2 : (j == 2) ? W3 : W4;
    d_Wb[idx] = __float2bfloat16(W[r]);
}

__global__ void convert_wsmall(const float* __restrict__ g0, const float* __restrict__ g1,
                               const float* __restrict__ g2, const float* __restrict__ g3,
                               const float* __restrict__ q0, const float* __restrict__ q1,
                               const float* __restrict__ q2, const float* __restrict__ q3) {
    int idx = blockIdx.x * blockDim.x + threadIdx.x;
    if (idx < 4 * 49152) {
        int m = idx / 49152, r = idx % 49152;
        const float* W = (m == 0) ? g0 : (m == 1) ? g1 : (m == 2) ? g2 : g3;
        d_Wgb[idx] = __float2bfloat16(W[r]);
    } else if (idx < 4 * 49152 + 4 * 16384) {
        int k = idx - 4 * 49152;
        int m = k / 16384, r = k % 16384;
        const float* W = (m == 0) ? q0 : (m == 1) ? q1 : (m == 2) ? q2 : q3;
        d_WQb[k] = __float2bfloat16(W[r]);
    }
}

__global__ void hmean_kernel(const float* __restrict__ h) {
    int b = blockIdx.x, t = threadIdx.x;                 // 512 threads
    int e = t & 127, q = t >> 7;
    __shared__ float part[4][128];
    float s = 0.f;
    for (int g = q * 500; g < (q + 1) * 500; g++) {
        size_t idx = ((size_t)b * GS + g) * E + e;
        float v = h[idx];
        s += v;
        d_hb[idx] = __float2bfloat16(v);
    }
    part[q][e] = s;
    __syncthreads();
    if (t < 128)
        d_hmean[b * E + t] = (part[0][t] + part[1][t] + part[2][t] + part[3][t]) * (1.0f / GS);
}

__global__ void vtt_kernel(const int* __restrict__ vt, const int* __restrict__ fixed_action) {
    int idx = blockIdx.x * 256 + threadIdx.x;            // grid 1000
    if (idx >= BS * GS) return;
    int b = idx / GS;
    int vta = vt[b * GS + fixed_action[b * KM]];
    int d = vt[idx] - vta;
    d_vtt[idx] = (d + GS) % GS;                          // Python floored mod
}

__global__ void init_kernel(const float* __restrict__ W_init, const float* __restrict__ b_init) {
    int b = blockIdx.x, t = threadIdx.x;                 // 128 threads
    __shared__ __align__(16) float sm[E];
    sm[t] = d_hmean[b * E + t];
    __syncthreads();
    float acc = b_init[t];
    const float4* w = (const float4*)(W_init + t * E);
    const float4* x = (const float4*)sm;
#pragma unroll 8
    for (int e4 = 0; e4 < E / 4; e4++) {
        float4 a = w[e4], v = x[e4];
        acc = fmaf(a.x, v.x, acc); acc = fmaf(a.y, v.y, acc);
        acc = fmaf(a.z, v.z, acc); acc = fmaf(a.w, v.w, acc);
    }
    d_q1[b * E + t] = acc;
    d_q2[b * E + t] = acc;
}

// ---- full 4-iteration integer bookkeeping simulation (one thread per b) ----
__global__ void precompute_kernel(const int* __restrict__ rec,
                                  const int* __restrict__ fixed_action) {
    int b = threadIdx.x;          // <<<1,128>>>
    if (b >= BS) return;
    const int bG = b * GS;
    int stopped = 1, nol = -1;
    int ai[4] = {0, 0, 0, 0};
    int kl[5] = {0, 0, 0, 0, 0};
    int kr[4] = {0, 0, 0, 0};
#pragma unroll
    for (int i = 0; i < KM; i++) {
        int stop_old = stopped;
        int action = (i > 0 && stop_old) ? ai[0] : fixed_action[b * KM + i];

        d_gact[i * BS + b] = action;
        d_gstopold[i * BS + b] = stop_old;
        d_gnolmod[i * BS + b] = ((nol % GS) + GS) % GS;

        int nna = rec[bG + action];
        ai[i] = action;
        if (stop_old) kl[i] = action;
        int krm1 = ((i - 1) + KM) % KM;
        if (!stop_old) kr[krm1] = action;
        kl[i + 1] = nna;

        int eq = (action == nol) ? 1 : 0;
        int stop_new = (i == 0) ? eq : (stop_old | eq);
        if (stop_new) {
            kl[i] = kl[((i - 1) + 5) % 5];
            kr[i] = kr[krm1];
        }
        stopped = stop_new;
        nol = stop_new ? -1 : nna;
        int ai0 = ai[0];

        if (i + 1 < KM) {
            d_mva[(i + 1) * BS + b] = d_vtt[bG + action];
            d_mstopnew[(i + 1) * BS + b] = stop_new;
            d_mact[(i + 1) * BS + b] = action;
            d_mallow[(i + 1) * BS + b] = (!stop_new && nna == ai0) ? 1 : 0;
            d_mai0[(i + 1) * BS + b] = ai0;
        }
        d_expsum4[i * BS + b] = 0.0f;
    }
#pragma unroll
    for (int i = 0; i < 4; i++) d_ai[b * 4 + i] = ai[i];
#pragma unroll
    for (int i = 0; i < 5; i++) d_kl[b * 5 + i] = kl[i];
#pragma unroll
    for (int i = 0; i < 4; i++) d_kr[b * 4 + i] = kr[i];
    d_stopped[b] = stopped;
}

// ---------------- pipelined bf16 MMA GEMM: Kc8 = e4m3(hb @ W^T) ----------------
// grid (8_n, 500_m): each block does 4 m-tiles of 128 rows, double-buffered A
// via cp.async groups (A(t+1) in flight during compute(t)). B loaded once.
#define A_TILE_B (128 * 136 * 2)     // 34816
#define B_TILE_B (64 * 136 * 2)      // 17408
#define GEMM_SMEM (2 * A_TILE_B + B_TILE_B)   // 87040
__global__ void __launch_bounds__(256) gemm_kernel() {
    extern __shared__ __align__(16) char smem_raw[];
    __nv_bfloat16 (*Abuf[2])[136] = {
        (__nv_bfloat16(*)[136])smem_raw,
        (__nv_bfloat16(*)[136])(smem_raw + A_TILE_B)
    };
    __nv_bfloat16 (*Bs)[136] = (__nv_bfloat16(*)[136])(smem_raw + 2 * A_TILE_B);
    const int t = threadIdx.x;
    const int warp = t >> 5, lane = t & 31;
    const int n0 = blockIdx.x * 64;
    const int mbase = blockIdx.y * 512;
    const int wm = (warp >> 1) * 32, wn = (warp & 1) * 32;

    // prefetch tile0 (A + B) -> group0 ; tile1 -> group1
#pragma unroll
    for (int i = t; i < 128 * 16; i += 256) {
        int row = i >> 4, c8 = i & 15;
        cp_async16(&Abuf[0][row][c8 * 8], d_hb + (size_t)(mbase + row) * 128 + c8 * 8);
    }
#pragma unroll
    for (int i = t; i < 64 * 16; i += 256) {
        int n = i >> 4, c8 = i & 15;
        cp_async16(&Bs[n][c8 * 8], d_Wb + (size_t)(n0 + n) * 128 + c8 * 8);
    }
    asm volatile("cp.async.commit_group;" ::: "memory");
#pragma unroll
    for (int i = t; i < 128 * 16; i += 256) {
        int row = i >> 4, c8 = i & 15;
        cp_async16(&Abuf[1][row][c8 * 8], d_hb + (size_t)(mbase + 128 + row) * 128 + c8 * 8);
    }
    asm volatile("cp.async.commit_group;" ::: "memory");

    const int a_row = (lane & 15), a_colh = (lane >> 4) * 8;
    const int b_row = ((lane >> 4) & 1) * 8 + (lane & 7);
    const int b_colh = ((lane >> 3) & 1) * 8;
    unsigned b_addr0 = (unsigned)__cvta_generic_to_shared(&Bs[wn + b_row][b_colh]);
    unsigned b_addr1 = (unsigned)__cvta_generic_to_shared(&Bs[wn + 16 + b_row][b_colh]);
    const int qr = lane >> 2, qc = lane & 3;

#pragma unroll
    for (int tile = 0; tile < 4; tile++) {
        if (tile == 3)
            asm volatile("cp.async.wait_group 0;" ::: "memory");
        else
            asm volatile("cp.async.wait_group 1;" ::: "memory");
        __syncthreads();

        __nv_bfloat16 (*As)[136] = Abuf[tile & 1];
        unsigned a_addr0 = (unsigned)__cvta_generic_to_shared(&As[wm + a_row][a_colh]);
        unsigned a_addr1 = (unsigned)__cvta_generic_to_shared(&As[wm + 16 + a_row][a_colh]);

        float c[2][4][4];
#pragma unroll
        for (int i = 0; i < 2; i++)
#pragma unroll
            for (int j = 0; j < 4; j++)
#pragma unroll
                for (int k = 0; k < 4; k++) c[i][j][k] = 0.f;

#pragma unroll
        for (int ks = 0; ks < 8; ks++) {
            unsigned koff = ks * 32;
            unsigned af0[4], af1[4], bf0[4], bf1[4];
            LDSM4(af0, a_addr0 + koff);
            LDSM4(af1, a_addr1 + koff);
            LDSM4(bf0, b_addr0 + koff);
            LDSM4(bf1, b_addr1 + koff);
            MMA16816(c[0][0], af0, bf0[0], bf0[1]);
            MMA16816(c[0][1], af0, bf0[2], bf0[3]);
            MMA16816(c[0][2], af0, bf1[0], bf1[1]);
            MMA16816(c[0][3], af0, bf1[2], bf1[3]);
            MMA16816(c[1][0], af1, bf0[0], bf0[1]);
            MMA16816(c[1][1], af1, bf0[2], bf0[3]);
            MMA16816(c[1][2], af1, bf1[0], bf1[1]);
            MMA16816(c[1][3], af1, bf1[2], bf1[3]);
        }

        int m0 = mbase + tile * 128;
#pragma unroll
        for (int mf = 0; mf < 2; mf++)
#pragma unroll
            for (int nf = 0; nf < 4; nf++) {
                int row = m0 + wm + mf * 16 + qr;
                int col = n0 + wn + nf * 8 + qc * 2;
                unsigned short p0 = fp8pack(c[mf][nf][0], c[mf][nf][1]);
                unsigned short p1 = fp8pack(c[mf][nf][2], c[mf][nf][3]);
                *(unsigned short*)(d_Kc8 + (size_t)row * 512 + col) = p0;
                *(unsigned short*)(d_Kc8 + (size_t)(row + 8) * 512 + col) = p1;
            }

        __syncthreads();   // all warps done with this buffer before refill
        if (tile + 2 < 4) {
            __nv_bfloat16 (*Anext)[136] = Abuf[tile & 1];
            int mn = mbase + (tile + 2) * 128;
#pragma unroll
            for (int i = t; i < 128 * 16; i += 256) {
                int row = i >> 4, c8 = i & 15;
                cp_async16(&Anext[row][c8 * 8], d_hb + (size_t)(mn + row) * 128 + c8 * 8);
            }
            asm volatile("cp.async.commit_group;" ::: "memory");
        }
    }
}

// ---------------- fused GRU chain + Q projections (r15, unchanged) ----------------
__global__ void __launch_bounds__(384) gruchain_kernel(
    const float* __restrict__ h, const float* __restrict__ init_query,
    const float* __restrict__ bih1, const float* __restrict__ bhh1,
    const float* __restrict__ bih2, const float* __restrict__ bhh2) {
    int b = blockIdx.x, r = blockIdx.y, t = threadIdx.x;   // 384 threads
    const float* bih = r ? bih2 : bih1;
    const float* bhh = r ? bhh2 : bhh1;

    __shared__ __align__(16) float sx[E], sq[E];
    __shared__ float gi[3 * E], gh[3 * E];
    if (t < E) sq[t] = (r ? d_q2 : d_q1)[b * E + t];

    const uint4* wi = (const uint4*)(d_Wgb + ((size_t)(r * 2) * 384 + t) * 128);
    const uint4* wh = (const uint4*)(d_Wgb + ((size_t)(r * 2 + 1) * 384 + t) * 128);

    for (int it = 0; it < KM; it++) {
        if (t < E) {
            float x;
            if (it == 0) {
                x = init_query[t];
            } else {
                int idx = (it - 1) * BS + b;
                int act = d_gact[idx];
                int gg = (r == 0) ? act : (d_gstopold[idx] ? act : d_gnolmod[idx]);
                x = h[((size_t)b * GS + gg) * E + t];
            }
            sx[t] = x;
        }
        __syncthreads();

        float a = bih[t], cg = bhh[t];
        const float4* x4 = (const float4*)sx;
        const float4* h4 = (const float4*)sq;
#pragma unroll 4
        for (int e8 = 0; e8 < E / 8; e8++) {
            uint4 wa = wi[e8], wb = wh[e8];
            DOT8(a, wa, x4 + e8 * 2);
            DOT8(cg, wb, h4 + e8 * 2);
        }
        gi[t] = a; gh[t] = cg;
        __syncthreads();

        if (t < E) {
            float rr = sigmoidf_(gi[t] + gh[t]);
            float z  = sigmoidf_(gi[E + t] + gh[E + t]);
            float n  = tanhf(gi[2 * E + t] + rr * gh[2 * E + t]);
            sq[t] = (1.0f - z) * n + z * sq[t];
        }
        __syncthreads();

        if (t < 256) {
            int jj = t >> 7, f = t & 127;
            int j = (r == 0) ? (jj ? 2 : 0) : (jj ? 3 : 1);
            const uint4* w = (const uint4*)(d_WQb + ((size_t)j * 128 + f) * 128);
            const float4* x = (const float4*)sq;
            float acc = 0.f;
#pragma unroll 4
            for (int e8 = 0; e8 < E / 8; e8++) {
                uint4 wa = w[e8];
                DOT8(acc, wa, x + e8 * 2);
            }
            d_Qp[((size_t)it * BS + b) * 512 + j * 128 + f] = acc;
        }
    }
}

// ---------------- mega score (half2 datapath; r15, unchanged) ----------------
__global__ void __launch_bounds__(256) mega_score_kernel(const int* __restrict__ last_action,
                                                         const float* __restrict__ V1,
                                                         const float* __restrict__ V2) {
    int b = blockIdx.x, t = threadIdx.x;
    int warp = t >> 5, lane = t & 31;
    __shared__ __half2 sQh[KM][4][64];
    __shared__ __half2 sVh[2][64];
    __shared__ float sE[KM][8];
    for (int i = t; i < KM * 256; i += 256) {
        int it = i >> 8, rem = i & 255;
        int seg = rem >> 6, f2 = rem & 63;
        const float* qp = d_Qp + ((size_t)it * BS + b) * 512 + seg * 128 + f2 * 2;
        sQh[it][seg][f2] = __floats2half2_rn(qp[0], qp[1]);
    }
    if (t < 128) {
        int seg = t >> 6, f2 = t & 63;
        const float* V = seg ? V2 : V1;
        sVh[seg][f2] = __floats2half2_rn(V[f2 * 2], V[f2 * 2 + 1]);
    }
    __syncthreads();

    int g0 = blockIdx.y * 16 + warp * 2;
    const unsigned char* __restrict__ Kc = d_Kc8 + ((size_t)b * GS + g0) * 512;
    int f0 = lane * 4;
    unsigned ua1 = *(const unsigned*)(Kc + f0);
    unsigned ua2 = *(const unsigned*)(Kc + 128 + f0);
    unsigned ua3 = *(const unsigned*)(Kc + 256 + f0);
    unsigned ua4 = *(const unsigned*)(Kc + 384 + f0);
    unsigned ub1 = *(const unsigned*)(Kc + 512 + f0);
    unsigned ub2 = *(const unsigned*)(Kc + 640 + f0);
    unsigned ub3 = *(const unsigned*)(Kc + 768 + f0);
    unsigned ub4 = *(const unsigned*)(Kc + 896 + f0);

    __half2 k1h[2], k2h[2], k3h[2], k4h[2];
    __half2 l1h[2], l2h[2], l3h[2], l4h[2];
    fp8x4_to_h2(ua1, k1h[0], k1h[1]); fp8x4_to_h2(ua2, k2h[0], k2h[1]);
    fp8x4_to_h2(ua3, k3h[0], k3h[1]); fp8x4_to_h2(ua4, k4h[0], k4h[1]);
    fp8x4_to_h2(ub1, l1h[0], l1h[1]); fp8x4_to_h2(ub2, l2h[0], l2h[1]);
    fp8x4_to_h2(ub3, l3h[0], l3h[1]); fp8x4_to_h2(ub4, l4h[0], l4h[1]);

    int v0 = 0, v1 = 0, la = 0;
    if (lane == 0) {
        v0 = d_vtt[b * GS + g0];
        v1 = d_vtt[b * GS + g0 + 1];
        la = last_action[b];
    }

#pragma unroll
    for (int it = 0; it < KM; it++) {
        __half2 accA = __floats2half2_rn(0.f, 0.f);
        __half2 accB = __floats2half2_rn(0.f, 0.f);
#pragma unroll
        for (int ii = 0; ii < 2; ii++) {
            int p = lane * 2 + ii;
            __half2 q0 = sQh[it][0][p], q1 = sQh[it][1][p];
            __half2 q2 = sQh[it][2][p], q3 = sQh[it][3][p];
            __half2 vv1 = sVh[0][p], vv2 = sVh[1][p];
            accA = __hfma2(vv1, tanh_h2(__hfma2(k3h[ii], q2, __hadd2(k1h[ii], q0))), accA);
            accA = __hfma2(vv2, tanh_h2(__hfma2(k4h[ii], q3, __hadd2(k2h[ii], q1))), accA);
            accB = __hfma2(vv1, tanh_h2(__hfma2(l3h[ii], q2, __hadd2(l1h[ii], q0))), accB);
            accB = __hfma2(vv2, tanh_h2(__hfma2(l4h[ii], q3, __hadd2(l2h[ii], q1))), accB);
        }
        float2 fa = __half22float2(accA);
        float2 fb = __half22float2(accB);
        float s0 = fa.x + fa.y, s1 = fb.x + fb.y;
#pragma unroll
        for (int o = 16; o; o >>= 1) {
            s0 += __shfl_xor_sync(0xFFFFFFFFu, s0, o);
            s1 += __shfl_xor_sync(0xFFFFFFFFu, s1, o);
        }
        if (lane == 0) {
            float lg0 = tanh_fast(s0) * CLIPV;
            float lg1 = tanh_fast(s1) * CLIPV;
            bool m0, m1;
            if (it == 0) {
                m0 = (g0 == la); m1 = (g0 + 1 == la);
            } else {
                int mva  = d_mva[it * BS + b];
                int msn  = d_mstopnew[it * BS + b];
                int mact = d_mact[it * BS + b];
                int mal  = d_mallow[it * BS + b];
                int mai0 = d_mai0[it * BS + b];
                m0 = (v0 <= mva); m1 = (v1 <= mva);
                if (it == 1) { m0 = m0 || (v0 > GS - 2); m1 = m1 || (v1 > GS - 2); }
                if (msn) { if (g0 == mact) m0 = false; if (g0 + 1 == mact) m1 = false; }
                if (mal) { if (g0 == mai0) m0 = false; if (g0 + 1 == mai0) m1 = false; }
            }
            int act = d_gact[it * BS + b];
            if (g0 == act)     d_logact4[it * BS + b] = m0 ? NEGV : lg0;
            if (g0 + 1 == act) d_logact4[it * BS + b] = m1 ? NEGV : lg1;
            sE[it][warp] = (m0 ? 0.f : expf(lg0 - CLIPV)) + (m1 ? 0.f : expf(lg1 - CLIPV));
        }
    }
    __syncthreads();
    if (t < KM) {
        float e = 0.f;
#pragma unroll
        for (int i = 0; i < 8; i++) e += sE[t][i];
        atomicAdd(&d_expsum4[t * BS + b], e);
    }
}

// ---------------- output (loss folded in) ----------------
__global__ void out_kernel(float* __restrict__ out) {
    int idx = blockIdx.x * 256 + threadIdx.x;
    if (idx < BS * 12) {
        int b = idx / 12, j = idx % 12;
        int v;
        if (j < 4) v = d_ai[b * 4 + j];
        else if (j < 8) v = d_kl[b * 5 + (j - 4)];
        else {
            int jj = j - 8;
            if (jj == 3 && !d_stopped[b]) v = d_kl[b * 5 + 4];  // post-loop kr fix
            else v = d_kr[b * 4 + jj];
        }
        out[idx] = (float)v;
    } else if (idx < BS * 12 + BS) {
        int b = idx - BS * 12;
        float ll = 0.f;
#pragma unroll
        for (int it = 0; it < KM; it++) {
            float es = d_expsum4[it * BS + b];
            float loss = (es > 0.0f) ? (d_logact4[it * BS + b] - (CLIPV + logf(es)))
                                     : (-logf((float)GS));
            if (it == 0 || !d_gstopold[it * BS + b]) ll += loss;
        }
        out[idx] = ll;
    }
}

// ---------------- launch ----------------
extern "C" void kernel_launch(void* const* d_in, const int* in_sizes, int n_in,
                              void* d_out, int out_size) {
    (void)in_sizes; (void)n_in; (void)out_size;
    const float* h            = (const float*)d_in[0];
    const int*   rec          = (const int*)  d_in[1];
    /* context2 d_in[2] unused */
    const int*   visited_time = (const int*)  d_in[3];
    const int*   last_action  = (const int*)  d_in[4];
    const int*   fixed_action = (const int*)  d_in[5];
    const float* W_K1 = (const float*)d_in[6];
    const float* W_K2 = (const float*)d_in[7];
    const float* W_K3 = (const float*)d_in[8];
    const float* W_K4 = (const float*)d_in[9];
    const float* W_Q1 = (const float*)d_in[10];
    const float* W_Q2 = (const float*)d_in[11];
    const float* W_Q3 = (const float*)d_in[12];
    const float* W_Q4 = (const float*)d_in[13];
    const float* W_init     = (const float*)d_in[14];
    const float* b_init     = (const float*)d_in[15];
    const float* V1         = (const float*)d_in[16];
    const float* V2         = (const float*)d_in[17];
    const float* init_query = (const float*)d_in[18];
    const float* r1_Wih = (const float*)d_in[19];
    const float* r1_Whh = (const float*)d_in[20];
    const float* r1_bih = (const float*)d_in[21];
    const float* r1_bhh = (const float*)d_in[22];
    const float* r2_Wih = (const float*)d_in[23];
    const float* r2_Whh = (const float*)d_in[24];
    const float* r2_bih = (const float*)d_in[25];
    const float* r2_bhh = (const float*)d_in[26];

    static int smem_set = 0;
    if (!smem_set) {
        cudaFuncSetAttribute(gemm_kernel, cudaFuncAttributeMaxDynamicSharedMemorySize,
                             GEMM_SMEM);
        smem_set = 1;
    }

    convert_w<<<256, 256>>>(W_K1, W_K2, W_K3, W_K4);
    convert_wsmall<<<1024, 256>>>(r1_Wih, r1_Whh, r2_Wih, r2_Whh,
                                  W_Q1, W_Q2, W_Q3, W_Q4);
    hmean_kernel<<<BS, 512>>>(h);
    vtt_kernel<<<1000, 256>>>(visited_time, fixed_action);
    init_kernel<<<BS, 128>>>(W_init, b_init);
    precompute_kernel<<<1, 128>>>(rec, fixed_action);
    gemm_kernel<<<dim3(8, 500), 256, GEMM_SMEM>>>();
    gruchain_kernel<<<dim3(BS, 2), 384>>>(h, init_query,
                                          r1_bih, r1_bhh, r2_bih, r2_bhh);
    mega_score_kernel<<<dim3(BS, 125), 256>>>(last_action, V1, V2);
    out_kernel<<<7, 256>>>((float*)d_out);
}